// round 13
// baseline (speedup 1.0000x reference)
#include <cuda_runtime.h>
#include <math.h>

#define D_   64
#define T_   128
#define B_   64
#define R_   20
#define SEE_ 10
#define H_   4
#define C_   4
#define NT   512
#define G_   2          // batch elements per block in k4

typedef unsigned long long ull;

// ---------------- precomputed per-(t,b) data ----------------
__device__ __align__(16) float g_kk [ (size_t)B_*T_*2560 ];
__device__ __align__(16) float g_hv [ (size_t)B_*T_*2304 ];
__device__ __align__(16) float g_bgr[ (size_t)B_*T_*12 ];
__device__ __align__(16) float g_qv [ (size_t)B_*T_*256 ];
__device__ __align__(16) float g_v  [ (size_t)B_*(T_+1)*128 ];
__device__ __align__(16) float g_pr [ (size_t)B_*T_*132 ];
__device__ __align__(16) float g_pn [ (size_t)B_*T_*132 ];

// ---------------- helpers ----------------
__device__ __forceinline__ void ffma2(ull& a, ull x, ull w){
  asm("fma.rn.f32x2 %0, %1, %2, %0;" : "+l"(a) : "l"(x), "l"(w));
}
__device__ __forceinline__ ull pack2(float lo, float hi){
  ull r; asm("mov.b64 %0, {%1,%2};" : "=l"(r) : "f"(lo), "f"(hi)); return r;
}
__device__ __forceinline__ void unpack2(ull a, float& lo, float& hi){
  asm("mov.b64 {%0,%1}, %2;" : "=f"(lo), "=f"(hi) : "l"(a));
}
__device__ __forceinline__ float sigmoidf_(float x){ return 1.0f/(1.0f+expf(-x)); }
__device__ __forceinline__ void cp16(void* sdst, const void* gsrc){
  unsigned sa;
  asm("{.reg .u64 t; cvta.to.shared.u64 t, %1; cvt.u32.u64 %0, t;}" : "=r"(sa) : "l"(sdst));
  asm volatile("cp.async.cg.shared.global [%0], [%1], 16;" :: "r"(sa), "l"(gsrc));
}

// ================= K1: bg gather + kk GEMV =================
__global__ void __launch_bounds__(256,4) k1_kernel(
  const int* __restrict__ bg_index, const int* __restrict__ mem_prob_ids,
  const int* __restrict__ mem_resp, const int* __restrict__ mem_concepts,
  const float* __restrict__ states_mem, const float* __restrict__ concept_emb,
  const float* __restrict__ prob_emb,
  const float* __restrict__ W_bg, const float* __restrict__ b_bg)
{
  __shared__ __align__(16) float hvT[2304];
  const int tb = blockIdx.x;
  const int t = tb / B_, b = tb - t*B_;
  const int tid = threadIdx.x;

  for (int i = tid; i < 192*2; i += 256) hvT[(i>>1)*12 + 10 + (i&1)] = 0.f;
  for (int i = tid; i < SEE_*3*D_; i += 256){
    int s = i / (3*D_);
    int k = i - s*3*D_;
    int idx = bg_index[(t*B_ + b)*R_ + s];
    float val;
    if (k < D_){
      val = states_mem[(size_t)idx*D_ + k];
    } else if (k < 2*D_){
      int d = k - D_;
      float ss = 0.f; int cnt = 0;
      #pragma unroll
      for (int c = 0; c < C_; ++c){
        int kc = mem_concepts[(size_t)idx*C_ + c];
        if (kc > 0){ ss += concept_emb[(size_t)(kc-1)*D_ + d]; cnt++; }
      }
      val = ss / (cnt ? (float)cnt : 1.f);
    } else {
      int d  = k - 2*D_;
      int mp = mem_prob_ids[idx];
      val = (mp > 0) ? prob_emb[(size_t)(mp-1)*D_ + d] : 0.f;
    }
    hvT[k*12 + s] = val;
  }
  if (tid < SEE_){
    int idx = bg_index[(t*B_ + b)*R_ + tid];
    g_bgr[(size_t)tb*12 + tid] = (float)mem_resp[idx];
  }
  __syncthreads();

  for (int i = tid; i < 2304; i += 256)
    g_hv[(size_t)tb*2304 + i] = hvT[i];

  {
    int hh = tid >> 6, d = tid & 63;
    const float* Wg = W_bg + (size_t)hh*(3*D_*D_) + d;
    ull a0=0,a1=0,a2=0,a3=0,a4=0;
    #pragma unroll 2
    for (int k0 = 0; k0 < 192; k0 += 8){
      float w[8];
      #pragma unroll
      for (int u = 0; u < 8; ++u) w[u] = Wg[(size_t)(k0+u)*64];
      #pragma unroll
      for (int u = 0; u < 8; ++u){
        ull ww = pack2(w[u], w[u]);
        const ull* hv = reinterpret_cast<const ull*>(hvT + (k0+u)*12);
        ffma2(a0, hv[0], ww); ffma2(a1, hv[1], ww); ffma2(a2, hv[2], ww);
        ffma2(a3, hv[3], ww); ffma2(a4, hv[4], ww);
      }
    }
    float bb = b_bg[hh*64 + d];
    float lo, hi;
    float* o = g_kk + (size_t)tb*2560 + (size_t)hh*10*64 + d;
    unpack2(a0, lo, hi); o[0*64]=bb+lo; o[1*64]=bb+hi;
    unpack2(a1, lo, hi); o[2*64]=bb+lo; o[3*64]=bb+hi;
    unpack2(a2, lo, hi); o[4*64]=bb+lo; o[5*64]=bb+hi;
    unpack2(a3, lo, hi); o[6*64]=bb+lo; o[7*64]=bb+hi;
    unpack2(a4, lo, hi); o[8*64]=bb+lo; o[9*64]=bb+hi;
  }
}

// ================= K2: v + qv =================
__global__ void __launch_bounds__(128,8) k2_kernel(
  const int* __restrict__ prob_id, const int* __restrict__ skills,
  const float* __restrict__ concept_emb, const float* __restrict__ prob_emb,
  const float* __restrict__ W_batch, const float* __restrict__ b_batch)
{
  __shared__ __align__(16) float v[128];
  const int tb = blockIdx.x;
  const int t = tb / B_, b = tb - t*B_;
  const int tid = threadIdx.x;

  float val;
  if (tid < D_){
    float s = 0.f; int cnt = 0;
    #pragma unroll
    for (int c = 0; c < C_; ++c){
      int k = skills[(t*B_ + b)*C_ + c];
      if (k > 0){ s += concept_emb[(size_t)(k-1)*D_ + tid]; cnt++; }
    }
    val = s / (cnt ? (float)cnt : 1.f);
  } else {
    int pid = prob_id[t*B_ + b];
    val = (pid > 0) ? prob_emb[(size_t)(pid-1)*D_ + (tid - D_)] : 0.f;
  }
  v[tid] = val;
  g_v[((size_t)b*(T_+1) + t + 1)*128 + tid] = val;
  if (t == 0) g_v[((size_t)b*(T_+1))*128 + tid] = 0.f;
  __syncthreads();

  int hh = tid >> 5, dp = tid & 31;
  const ull* Wb = reinterpret_cast<const ull*>(W_batch + (size_t)hh*(3*D_*D_)) + dp;
  ull acc = 0;
  const float4* xv = reinterpret_cast<const float4*>(v);
  #pragma unroll 2
  for (int k4 = 0; k4 < 32; ++k4){
    float4 x = xv[k4]; int k = 64 + k4*4;
    ull w0 = Wb[(size_t)(k+0)*32], w1 = Wb[(size_t)(k+1)*32];
    ull w2 = Wb[(size_t)(k+2)*32], w3 = Wb[(size_t)(k+3)*32];
    ffma2(acc, pack2(x.x,x.x), w0); ffma2(acc, pack2(x.y,x.y), w1);
    ffma2(acc, pack2(x.z,x.z), w2); ffma2(acc, pack2(x.w,x.w), w3);
  }
  float lo, hi; unpack2(acc, lo, hi);
  g_qv[(size_t)tb*256 + hh*64 + 2*dp]     = b_batch[hh*64 + 2*dp]     + lo;
  g_qv[(size_t)tb*256 + hh*64 + 2*dp + 1] = b_batch[hh*64 + 2*dp + 1] + hi;
}

// ================= K3: history softmax weights =================
__global__ void __launch_bounds__(512,1) k3_kernel(const int* __restrict__ response)
{
  extern __shared__ float k3s[];
  float* vv   = k3s;
  float* resp = k3s + (T_+1)*129;
  const int b   = blockIdx.x;
  const int tid = threadIdx.x;
  const int lane = tid & 31, wid = tid >> 5;
  const float inv_s128 = 1.0f/sqrtf(128.0f);

  for (int i = tid; i < (T_+1)*128; i += 512){
    int row = i >> 7, col = i & 127;
    vv[row*129 + col] = g_v[(size_t)b*(T_+1)*128 + i];
  }
  for (int j = tid; j <= T_; j += 512)
    resp[j] = (j == 0) ? 0.f : (float)response[(j-1)*B_ + b];
  __syncthreads();

  for (int t = wid; t < T_; t += 16){
    const float* vt = vv + (t+1)*129;
    float scv[4]; int nj = 0;
    for (int j = lane; j <= t; j += 32){
      const float* vj = vv + j*129;
      float a = 0.f;
      #pragma unroll 4
      for (int k = 0; k < 128; ++k) a += vt[k]*vj[k];
      scv[nj++] = a * inv_s128;
    }
    float mx = -1e30f;
    for (int i = 0; i < nj; ++i) mx = fmaxf(mx, scv[i]);
    #pragma unroll
    for (int o = 16; o; o >>= 1) mx = fmaxf(mx, __shfl_xor_sync(0xffffffffu, mx, o));
    float sum = 0.f;
    for (int i = 0; i < nj; ++i){ scv[i] = expf(scv[i]-mx); sum += scv[i]; }
    #pragma unroll
    for (int o = 16; o; o >>= 1) sum += __shfl_xor_sync(0xffffffffu, sum, o);
    float inv = 1.f/sum;
    int i = 0;
    for (int j = lane; j <= t; j += 32, ++i){
      float p = scv[i]*inv;
      float rb = resp[j];
      g_pr[((size_t)b*T_ + t)*132 + j] = p*rb;
      g_pn[((size_t)b*T_ + t)*132 + j] = p*(1.f-rb);
    }
  }
}

// ================= K4: sequential recurrence, G_=2 batch/block =================
struct __align__(16) SmemSeq {
  alignas(16) float h[G_][D_];
  alignas(16) float q[G_][256];
  alignas(16) float his_atts[G_][128];
  alignas(16) float hisP[G_][384];
  alignas(16) float bg_atts[G_][384];
  alignas(16) float x10[G_][640];
  alignas(16) float gru_in[G_][256];
  alignas(16) float gx[G_][192];
  alignas(16) float gh[G_][192];
  alignas(16) float hbuf[G_][(T_+1)*D_];
  alignas(16) ull   part[G_][512];
  alignas(16) float kk[G_][2][2560];
  alignas(16) float hvT[G_][2][2304];
  alignas(16) float v[G_][2][128];
  alignas(16) float qv[G_][2][256];
  alignas(16) float pr[G_][2][132];
  alignas(16) float pn[G_][2][132];
  alignas(16) float bgr[G_][2][12];
  float logit[G_][40], att[G_][40], ws[G_][12];
  float dw0, dw1;
};

__device__ __forceinline__ void do_prefetch(SmemSeq* sm, int bg, int g, int tn, int nb,
                                            int idx, int nthr)
{
  size_t tb = (size_t)tn*B_ + bg;
  float* d0 = sm->kk[g][nb];  const float* s0 = g_kk + tb*2560;
  float* d1 = sm->hvT[g][nb]; const float* s1 = g_hv + tb*2304;
  float* d2 = sm->v[g][nb];   const float* s2 = g_v  + ((size_t)bg*(T_+1) + tn + 1)*128;
  float* d3 = sm->qv[g][nb];  const float* s3 = g_qv + tb*256;
  float* d4 = sm->pr[g][nb];  const float* s4 = g_pr + ((size_t)bg*T_ + tn)*132;
  float* d5 = sm->pn[g][nb];  const float* s5 = g_pn + ((size_t)bg*T_ + tn)*132;
  float* d6 = sm->bgr[g][nb]; const float* s6 = g_bgr + tb*12;
  for (int u = idx; u < 640; u += nthr) cp16(d0+4*u, s0+4*u);
  for (int u = idx; u < 576; u += nthr) cp16(d1+4*u, s1+4*u);
  for (int u = idx; u <  32; u += nthr) cp16(d2+4*u, s2+4*u);
  for (int u = idx; u <  64; u += nthr) cp16(d3+4*u, s3+4*u);
  for (int u = idx; u <  33; u += nthr) cp16(d4+4*u, s4+4*u);
  for (int u = idx; u <  33; u += nthr) cp16(d5+4*u, s5+4*u);
  for (int u = idx; u <   3; u += nthr) cp16(d6+4*u, s6+4*u);
}

__global__ void __launch_bounds__(NT,1) k4_kernel(
  const int* __restrict__ response,
  const float* __restrict__ W_pred, const float* __restrict__ b_pred,
  const float* __restrict__ W_ih, const float* __restrict__ W_hh,
  const float* __restrict__ b_ih, const float* __restrict__ b_hh,
  const float* __restrict__ W_batch,
  const float* __restrict__ W_bgint, const float* __restrict__ b_bgint,
  const float* __restrict__ W_hisint, const float* __restrict__ b_hisint,
  const float* __restrict__ W_inmap, const float* __restrict__ b_inmap,
  const float* __restrict__ dir_w, const float* __restrict__ heads_map,
  float* __restrict__ out)
{
  extern __shared__ unsigned char smraw[];
  SmemSeq* sm = reinterpret_cast<SmemSeq*>(smraw);
  const int b0   = blockIdx.x * G_;
  const int tid  = threadIdx.x;
  const int lane = tid & 31;
  const int wid  = tid >> 5;
  const float inv_s192 = 1.0f/sqrtf(192.0f);

  if (tid < G_*D_){
    int g = tid >> 6, d = tid & 63;
    sm->h[g][d] = 0.f; sm->hbuf[g][d] = 0.f;
  }
  if (tid == NT-1){
    float w0 = dir_w[0], w1 = dir_w[1];
    float m  = fmaxf(w0, w1);
    float e0 = expf(w0 - m), e1 = expf(w1 - m);
    sm->dw0 = e0/(e0+e1); sm->dw1 = e1/(e0+e1);
  }
  { int g = tid >= 256; do_prefetch(sm, b0+g, g, 0, 0, tid & 255, 256); }
  asm volatile("cp.async.commit_group;");
  __syncthreads();

  for (int t = 0; t < T_; ++t){
    const int cur = t & 1, nxt = cur ^ 1;
    asm volatile("cp.async.wait_group 0;");
    __syncthreads();

    // ===== P0: q h-part (0..127, both g) | his_atts (128..383) | prefetch (384..511) =====
    if (tid < 128){
      int hh = tid >> 5, dp = tid & 31;
      const ull* Wb = reinterpret_cast<const ull*>(W_batch + (size_t)hh*(3*D_*D_)) + dp;
      ull a0 = 0, a1 = 0;
      const float4* x0 = reinterpret_cast<const float4*>(sm->h[0]);
      const float4* x1 = reinterpret_cast<const float4*>(sm->h[1]);
      #pragma unroll 2
      for (int k4 = 0; k4 < 16; ++k4){
        float4 xa = x0[k4], xb = x1[k4]; int k = k4*4;
        ull w0 = Wb[(size_t)(k+0)*32], w1 = Wb[(size_t)(k+1)*32];
        ull w2 = Wb[(size_t)(k+2)*32], w3 = Wb[(size_t)(k+3)*32];
        ffma2(a0, pack2(xa.x,xa.x), w0); ffma2(a1, pack2(xb.x,xb.x), w0);
        ffma2(a0, pack2(xa.y,xa.y), w1); ffma2(a1, pack2(xb.y,xb.y), w1);
        ffma2(a0, pack2(xa.z,xa.z), w2); ffma2(a1, pack2(xb.z,xb.z), w2);
        ffma2(a0, pack2(xa.w,xa.w), w3); ffma2(a1, pack2(xb.w,xb.w), w3);
      }
      float lo, hi;
      unpack2(a0, lo, hi);
      sm->q[0][hh*64 + 2*dp]   = sm->qv[0][cur][hh*64 + 2*dp]   + lo;
      sm->q[0][hh*64 + 2*dp+1] = sm->qv[0][cur][hh*64 + 2*dp+1] + hi;
      unpack2(a1, lo, hi);
      sm->q[1][hh*64 + 2*dp]   = sm->qv[1][cur][hh*64 + 2*dp]   + lo;
      sm->q[1][hh*64 + 2*dp+1] = sm->qv[1][cur][hh*64 + 2*dp+1] + hi;
    } else if (tid < 384){
      int idx = tid - 128;
      int g = idx >> 7, u = idx & 127, d = u & 63;
      const float* w = (u < 64) ? sm->pr[g][cur] : sm->pn[g][cur];
      const float* hb = sm->hbuf[g];
      float a0 = 0.f, a1 = 0.f;
      int j = 0;
      for (; j + 1 <= t; j += 2){
        a0 += w[j]  *hb[j*D_ + d];
        a1 += w[j+1]*hb[(j+1)*D_ + d];
      }
      if (j <= t) a0 += w[j]*hb[j*D_ + d];
      sm->his_atts[g][u] = a0 + a1;
    } else {
      if (t + 1 < T_){
        int g = tid >= 448;
        do_prefetch(sm, b0+g, g, t+1, nxt, tid & 63, 64);
        asm volatile("cp.async.commit_group;");
      }
    }
    __syncthreads();

    // ===== P1: logits (warps 0..7) | W_hisint GEMV (256..447, both g) =====
    if (wid < 8){
      int g = wid >> 2, w4 = wid & 3;
      for (int p = w4; p < 40; p += 4){
        int hh = p / 10;
        float a = sm->kk[g][cur][p*64 + lane]      * sm->q[g][hh*64 + lane]
                + sm->kk[g][cur][p*64 + 32 + lane] * sm->q[g][hh*64 + 32 + lane];
        #pragma unroll
        for (int o = 16; o; o >>= 1) a += __shfl_xor_sync(0xffffffffu, a, o);
        if (lane == 0) sm->logit[g][p] = a * inv_s192;
      }
    } else if (tid >= 256 && tid < 448){
      int i = tid - 256;
      const ull* Wh = reinterpret_cast<const ull*>(W_hisint) + i;
      ull a0 = 0, a1 = 0;
      const float4* x0 = reinterpret_cast<const float4*>(sm->his_atts[0]);
      const float4* x1 = reinterpret_cast<const float4*>(sm->his_atts[1]);
      #pragma unroll 2
      for (int k4 = 0; k4 < 32; ++k4){
        float4 xa = x0[k4], xb = x1[k4]; int k = k4*4;
        ull w0 = Wh[(size_t)(k+0)*192], w1 = Wh[(size_t)(k+1)*192];
        ull w2 = Wh[(size_t)(k+2)*192], w3 = Wh[(size_t)(k+3)*192];
        ffma2(a0, pack2(xa.x,xa.x), w0); ffma2(a1, pack2(xb.x,xb.x), w0);
        ffma2(a0, pack2(xa.y,xa.y), w1); ffma2(a1, pack2(xb.y,xb.y), w1);
        ffma2(a0, pack2(xa.z,xa.z), w2); ffma2(a1, pack2(xb.z,xb.z), w2);
        ffma2(a0, pack2(xa.w,xa.w), w3); ffma2(a1, pack2(xb.w,xb.w), w3);
      }
      float lo, hi;
      unpack2(a0, lo, hi); sm->hisP[0][2*i] = lo; sm->hisP[0][2*i+1] = hi;
      unpack2(a1, lo, hi); sm->hisP[1][2*i] = lo; sm->hisP[1][2*i+1] = hi;
    }
    __syncthreads();

    // ===== P2: att softmax + ws (warps 0..1, one per g) =====
    if (wid < G_){
      int g = wid;
      if (lane < H_){
        float mx = -1e30f;
        #pragma unroll
        for (int s = 0; s < SEE_; ++s) mx = fmaxf(mx, sm->logit[g][lane*10 + s]);
        float sum = 0.f;
        #pragma unroll
        for (int s = 0; s < SEE_; ++s){
          float e = expf(sm->logit[g][lane*10 + s] - mx);
          sm->att[g][lane*10 + s] = e; sum += e;
        }
        float inv = 1.f/sum;
        #pragma unroll
        for (int s = 0; s < SEE_; ++s) sm->att[g][lane*10 + s] *= inv;
      }
      __syncwarp();
      if (lane < SEE_){
        float a = 0.f;
        #pragma unroll
        for (int hh = 0; hh < H_; ++hh) a += heads_map[hh]*sm->att[g][hh*10 + lane];
        sm->ws[g][lane] = a;
      }
    }
    __syncthreads();

    // ===== P3: bg_atts (384 thr, both g) =====
    if (tid < 384){
      bool lo_ = tid < 192;
      int kidx = lo_ ? tid : tid - 192;
      #pragma unroll
      for (int g = 0; g < G_; ++g){
        float acc = 0.f;
        #pragma unroll
        for (int s = 0; s < SEE_; ++s){
          float r = sm->bgr[g][cur][s];
          acc += sm->ws[g][s] * sm->hvT[g][cur][kidx*12 + s] * (lo_ ? r : (1.f - r));
        }
        sm->bg_atts[g][tid] = acc;
      }
    }
    __syncthreads();

    // ===== P4: W_bgint GEMV (384 thr, both g) =====
    if (tid < 384){
      int seg = (tid >= 192);
      int jp  = tid - seg*192;
      const ull* Wb = reinterpret_cast<const ull*>(W_bgint) + jp;
      const float4* x0 = reinterpret_cast<const float4*>(sm->bg_atts[0]) + seg*48;
      const float4* x1 = reinterpret_cast<const float4*>(sm->bg_atts[1]) + seg*48;
      const int kb0 = seg*192;
      ull a0 = 0, a1 = 0;
      #pragma unroll 2
      for (int k4 = 0; k4 < 48; ++k4){
        float4 xa = x0[k4], xb = x1[k4]; int k = kb0 + k4*4;
        ull w0 = Wb[(size_t)(k+0)*192], w1 = Wb[(size_t)(k+1)*192];
        ull w2 = Wb[(size_t)(k+2)*192], w3 = Wb[(size_t)(k+3)*192];
        ffma2(a0, pack2(xa.x,xa.x), w0); ffma2(a1, pack2(xb.x,xb.x), w0);
        ffma2(a0, pack2(xa.y,xa.y), w1); ffma2(a1, pack2(xb.y,xb.y), w1);
        ffma2(a0, pack2(xa.z,xa.z), w2); ffma2(a1, pack2(xb.z,xb.z), w2);
        ffma2(a0, pack2(xa.w,xa.w), w3); ffma2(a1, pack2(xb.w,xb.w), w3);
      }
      sm->part[0][seg*192 + jp] = a0;
      sm->part[1][seg*192 + jp] = a1;
    }
    __syncthreads();
    // combine peer -> x10 (0..383) | v_resp (384..511, both g)
    if (tid < 384){
      int g = tid / 192, jj = tid - g*192, j = 2*jj;
      float l0,h0,l1,h1;
      unpack2(sm->part[g][jj],       l0, h0);
      unpack2(sm->part[g][192 + jj], l1, h1);
      sm->x10[g][j]   = sm->dw0*(l0+l1 + b_bgint[j])   + sm->dw1*(sm->hisP[g][j]   + b_hisint[j]);
      sm->x10[g][j+1] = sm->dw0*(h0+h1 + b_bgint[j+1]) + sm->dw1*(sm->hisP[g][j+1] + b_hisint[j+1]);
    } else {
      int u = tid - 384;
      #pragma unroll
      for (int g = 0; g < G_; ++g){
        float rf = (float)response[t*B_ + b0 + g];
        float vv = sm->v[g][cur][u];
        sm->x10[g][384 + u] = vv*rf;
        sm->x10[g][512 + u] = vv*(1.f - rf);
      }
    }
    __syncthreads();

    // ===== P5: gru_in (all 512, both g) =====
    {
      int seg = tid >> 7, jp = tid & 127;
      const ull* W = reinterpret_cast<const ull*>(W_inmap) + jp;
      const float4* x0 = reinterpret_cast<const float4*>(sm->x10[0]) + seg*40;
      const float4* x1 = reinterpret_cast<const float4*>(sm->x10[1]) + seg*40;
      const int k0 = seg*160;
      ull a0 = 0, a1 = 0;
      #pragma unroll 2
      for (int k4 = 0; k4 < 40; ++k4){
        float4 xa = x0[k4], xb = x1[k4]; int k = k0 + k4*4;
        ull w0 = W[(size_t)(k+0)*128], w1 = W[(size_t)(k+1)*128];
        ull w2 = W[(size_t)(k+2)*128], w3 = W[(size_t)(k+3)*128];
        ffma2(a0, pack2(xa.x,xa.x), w0); ffma2(a1, pack2(xb.x,xb.x), w0);
        ffma2(a0, pack2(xa.y,xa.y), w1); ffma2(a1, pack2(xb.y,xb.y), w1);
        ffma2(a0, pack2(xa.z,xa.z), w2); ffma2(a1, pack2(xb.z,xb.z), w2);
        ffma2(a0, pack2(xa.w,xa.w), w3); ffma2(a1, pack2(xb.w,xb.w), w3);
      }
      sm->part[0][seg*128 + jp] = a0;
      sm->part[1][seg*128 + jp] = a1;
    }
    __syncthreads();
    if (tid < 256){
      int g = tid >> 7, jp = tid & 127, j = 2*jp;
      float l0,h0,l1,h1,l2,h2,l3,h3;
      unpack2(sm->part[g][jp],        l0,h0);
      unpack2(sm->part[g][128 + jp],  l1,h1);
      unpack2(sm->part[g][256 + jp],  l2,h2);
      unpack2(sm->part[g][384 + jp],  l3,h3);
      sm->gru_in[g][j]   = b_inmap[j]   + l0+l1+l2+l3;
      sm->gru_in[g][j+1] = b_inmap[j+1] + h0+h1+h2+h3;
    }
    __syncthreads();

    // ===== P6: gx (0..383) | gh (384..479) | pred (480..511) =====
    if (tid < 384){
      int seg = tid/96, jp = tid - seg*96;
      const ull* W = reinterpret_cast<const ull*>(W_ih) + jp;
      const float4* x0 = reinterpret_cast<const float4*>(sm->gru_in[0]) + seg*16;
      const float4* x1 = reinterpret_cast<const float4*>(sm->gru_in[1]) + seg*16;
      const int k0 = seg*64;
      ull a0 = 0, a1 = 0;
      #pragma unroll 2
      for (int k4 = 0; k4 < 16; ++k4){
        float4 xa = x0[k4], xb = x1[k4]; int k = k0 + k4*4;
        ull w0 = W[(size_t)(k+0)*96], w1 = W[(size_t)(k+1)*96];
        ull w2 = W[(size_t)(k+2)*96], w3 = W[(size_t)(k+3)*96];
        ffma2(a0, pack2(xa.x,xa.x), w0); ffma2(a1, pack2(xb.x,xb.x), w0);
        ffma2(a0, pack2(xa.y,xa.y), w1); ffma2(a1, pack2(xb.y,xb.y), w1);
        ffma2(a0, pack2(xa.z,xa.z), w2); ffma2(a1, pack2(xb.z,xb.z), w2);
        ffma2(a0, pack2(xa.w,xa.w), w3); ffma2(a1, pack2(xb.w,xb.w), w3);
      }
      sm->part[0][seg*96 + jp] = a0;
      sm->part[1][seg*96 + jp] = a1;
    } else if (tid < 480){
      int jp = tid - 384;
      const ull* W = reinterpret_cast<const ull*>(W_hh) + jp;
      const float4* x0 = reinterpret_cast<const float4*>(sm->h[0]);
      const float4* x1 = reinterpret_cast<const float4*>(sm->h[1]);
      ull a0 = 0, a1 = 0;
      #pragma unroll 2
      for (int k4 = 0; k4 < 16; ++k4){
        float4 xa = x0[k4], xb = x1[k4]; int k = k4*4;
        ull w0 = W[(size_t)(k+0)*96], w1 = W[(size_t)(k+1)*96];
        ull w2 = W[(size_t)(k+2)*96], w3 = W[(size_t)(k+3)*96];
        ffma2(a0, pack2(xa.x,xa.x), w0); ffma2(a1, pack2(xb.x,xb.x), w0);
        ffma2(a0, pack2(xa.y,xa.y), w1); ffma2(a1, pack2(xb.y,xb.y), w1);
        ffma2(a0, pack2(xa.z,xa.z), w2); ffma2(a1, pack2(xb.z,xb.z), w2);
        ffma2(a0, pack2(xa.w,xa.w), w3); ffma2(a1, pack2(xb.w,xb.w), w3);
      }
      float lo, hi;
      unpack2(a0, lo, hi);
      sm->gh[0][2*jp] = b_hh[2*jp] + lo; sm->gh[0][2*jp+1] = b_hh[2*jp+1] + hi;
      unpack2(a1, lo, hi);
      sm->gh[1][2*jp] = b_hh[2*jp] + lo; sm->gh[1][2*jp+1] = b_hh[2*jp+1] + hi;
    } else {
      int l = tid - 480;
      #pragma unroll
      for (int g = 0; g < G_; ++g){
        float part = 0.f;
        #pragma unroll
        for (int i0 = 0; i0 < 9*D_; i0 += 32){
          int i = i0 + l;
          float xv = (i < 6*D_) ? sm->x10[g][i]
                   : ((i < 8*D_) ? sm->v[g][cur][i - 6*D_] : sm->h[g][i - 8*D_]);
          part += xv * W_pred[i];
        }
        #pragma unroll
        for (int o = 16; o; o >>= 1) part += __shfl_xor_sync(0xffffffffu, part, o);
        if (l == 0) out[(b0+g)*T_ + t] = part + b_pred[0];
      }
    }
    __syncthreads();
    if (tid < 192){
      int g = tid / 96, jj = tid - g*96, j = 2*jj;
      float l0,h0,l1,h1,l2,h2,l3,h3;
      unpack2(sm->part[g][jj],       l0,h0);
      unpack2(sm->part[g][96 + jj],  l1,h1);
      unpack2(sm->part[g][192 + jj], l2,h2);
      unpack2(sm->part[g][288 + jj], l3,h3);
      sm->gx[g][j]   = b_ih[j]   + l0+l1+l2+l3;
      sm->gx[g][j+1] = b_ih[j+1] + h0+h1+h2+h3;
    }
    __syncthreads();

    // ===== P7: GRU update (both g) =====
    if (tid < G_*D_){
      int g = tid >> 6, d = tid & 63;
      float r  = sigmoidf_(sm->gx[g][d]        + sm->gh[g][d]);
      float z  = sigmoidf_(sm->gx[g][D_ + d]   + sm->gh[g][D_ + d]);
      float n  = tanhf   (sm->gx[g][2*D_ + d]  + r*sm->gh[g][2*D_ + d]);
      float nh = (1.f - z)*n + z*sm->h[g][d];
      sm->h[g][d] = nh;
      sm->hbuf[g][(size_t)(t+1)*D_ + d] = nh;
    }
    __syncthreads();
  }
}

extern "C" void kernel_launch(void* const* d_in, const int* in_sizes, int n_in,
                              void* d_out, int out_size)
{
  (void)in_sizes; (void)n_in; (void)out_size;

  const int*   prob_id      = (const int*)  d_in[0];
  const int*   skills       = (const int*)  d_in[1];
  const int*   response     = (const int*)  d_in[2];
  const int*   bg_index     = (const int*)  d_in[3];
  const int*   mem_prob_ids = (const int*)  d_in[4];
  const int*   mem_resp     = (const int*)  d_in[5];
  const int*   mem_concepts = (const int*)  d_in[6];
  const float* states_mem   = (const float*)d_in[7];
  const float* concept_emb  = (const float*)d_in[8];
  const float* prob_emb     = (const float*)d_in[9];
  const float* W_pred       = (const float*)d_in[10];
  const float* b_pred       = (const float*)d_in[11];
  const float* W_ih         = (const float*)d_in[12];
  const float* W_hh         = (const float*)d_in[13];
  const float* b_ih         = (const float*)d_in[14];
  const float* b_hh         = (const float*)d_in[15];
  const float* W_batch      = (const float*)d_in[16];
  const float* b_batch      = (const float*)d_in[17];
  const float* W_bg         = (const float*)d_in[18];
  const float* b_bg         = (const float*)d_in[19];
  const float* W_bgint      = (const float*)d_in[20];
  const float* b_bgint      = (const float*)d_in[21];
  const float* W_hisint     = (const float*)d_in[22];
  const float* b_hisint     = (const float*)d_in[23];
  const float* W_inmap      = (const float*)d_in[24];
  const float* b_inmap      = (const float*)d_in[25];
  const float* dir_w        = (const float*)d_in[26];
  const float* heads_map    = (const float*)d_in[27];

  k1_kernel<<<T_*B_, 256>>>(bg_index, mem_prob_ids, mem_resp, mem_concepts,
                            states_mem, concept_emb, prob_emb, W_bg, b_bg);
  k2_kernel<<<T_*B_, 128>>>(prob_id, skills, concept_emb, prob_emb, W_batch, b_batch);

  int k3smem = ((T_+1)*129 + 132) * (int)sizeof(float);
  cudaFuncSetAttribute(k3_kernel, cudaFuncAttributeMaxDynamicSharedMemorySize, k3smem);
  k3_kernel<<<B_, 512, k3smem>>>(response);

  cudaFuncSetAttribute(k4_kernel, cudaFuncAttributeMaxDynamicSharedMemorySize,
                       (int)sizeof(SmemSeq));
  k4_kernel<<<B_/G_, NT, sizeof(SmemSeq)>>>(
    response, W_pred, b_pred, W_ih, W_hh, b_ih, b_hh, W_batch,
    W_bgint, b_bgint, W_hisint, b_hisint, W_inmap, b_inmap,
    dir_w, heads_map, (float*)d_out);
}

// round 14
// speedup vs baseline: 1.3902x; 1.3902x over previous
#include <cuda_runtime.h>
#include <math.h>

#define D_   64
#define T_   128
#define B_   64
#define R_   20
#define SEE_ 10
#define H_   4
#define C_   4
#define NT   1024

typedef unsigned long long ull;

// ---------------- precomputed per-(t,b) data ----------------
__device__ __align__(16) float g_kk [ (size_t)B_*T_*2560 ];
__device__ __align__(16) float g_hv [ (size_t)B_*T_*2304 ];
__device__ __align__(16) float g_bgr[ (size_t)B_*T_*12 ];
__device__ __align__(16) float g_qv [ (size_t)B_*T_*256 ];
__device__ __align__(16) float g_v  [ (size_t)B_*(T_+1)*128 ];
__device__ __align__(16) float g_pr [ (size_t)B_*T_*132 ];
__device__ __align__(16) float g_pn [ (size_t)B_*T_*132 ];

// ---------------- helpers ----------------
__device__ __forceinline__ void ffma2(ull& a, ull x, ull w){
  asm("fma.rn.f32x2 %0, %1, %2, %0;" : "+l"(a) : "l"(x), "l"(w));
}
__device__ __forceinline__ ull pack2(float lo, float hi){
  ull r; asm("mov.b64 %0, {%1,%2};" : "=l"(r) : "f"(lo), "f"(hi)); return r;
}
__device__ __forceinline__ void unpack2(ull a, float& lo, float& hi){
  asm("mov.b64 {%0,%1}, %2;" : "=f"(lo), "=f"(hi) : "l"(a));
}
__device__ __forceinline__ float sigmoidf_(float x){ return 1.0f/(1.0f+expf(-x)); }
__device__ __forceinline__ void cp16(void* sdst, const void* gsrc){
  unsigned sa;
  asm("{.reg .u64 t; cvta.to.shared.u64 t, %1; cvt.u32.u64 %0, t;}" : "=r"(sa) : "l"(sdst));
  asm volatile("cp.async.cg.shared.global [%0], [%1], 16;" :: "r"(sa), "l"(gsrc));
}

// ================= K1: bg gather + kk GEMV =================
__global__ void __launch_bounds__(256,4) k1_kernel(
  const int* __restrict__ bg_index, const int* __restrict__ mem_prob_ids,
  const int* __restrict__ mem_resp, const int* __restrict__ mem_concepts,
  const float* __restrict__ states_mem, const float* __restrict__ concept_emb,
  const float* __restrict__ prob_emb,
  const float* __restrict__ W_bg, const float* __restrict__ b_bg)
{
  __shared__ __align__(16) float hvT[2304];
  const int tb = blockIdx.x;
  const int t = tb / B_, b = tb - t*B_;
  const int tid = threadIdx.x;

  for (int i = tid; i < 192*2; i += 256) hvT[(i>>1)*12 + 10 + (i&1)] = 0.f;
  for (int i = tid; i < SEE_*3*D_; i += 256){
    int s = i / (3*D_);
    int k = i - s*3*D_;
    int idx = bg_index[(t*B_ + b)*R_ + s];
    float val;
    if (k < D_){
      val = states_mem[(size_t)idx*D_ + k];
    } else if (k < 2*D_){
      int d = k - D_;
      float ss = 0.f; int cnt = 0;
      #pragma unroll
      for (int c = 0; c < C_; ++c){
        int kc = mem_concepts[(size_t)idx*C_ + c];
        if (kc > 0){ ss += concept_emb[(size_t)(kc-1)*D_ + d]; cnt++; }
      }
      val = ss / (cnt ? (float)cnt : 1.f);
    } else {
      int d  = k - 2*D_;
      int mp = mem_prob_ids[idx];
      val = (mp > 0) ? prob_emb[(size_t)(mp-1)*D_ + d] : 0.f;
    }
    hvT[k*12 + s] = val;
  }
  if (tid < SEE_){
    int idx = bg_index[(t*B_ + b)*R_ + tid];
    g_bgr[(size_t)tb*12 + tid] = (float)mem_resp[idx];
  }
  __syncthreads();

  for (int i = tid; i < 2304; i += 256)
    g_hv[(size_t)tb*2304 + i] = hvT[i];

  {
    int hh = tid >> 6, d = tid & 63;
    const float* Wg = W_bg + (size_t)hh*(3*D_*D_) + d;
    ull a0=0,a1=0,a2=0,a3=0,a4=0;
    #pragma unroll 2
    for (int k0 = 0; k0 < 192; k0 += 8){
      float w[8];
      #pragma unroll
      for (int u = 0; u < 8; ++u) w[u] = Wg[(size_t)(k0+u)*64];
      #pragma unroll
      for (int u = 0; u < 8; ++u){
        ull ww = pack2(w[u], w[u]);
        const ull* hv = reinterpret_cast<const ull*>(hvT + (k0+u)*12);
        ffma2(a0, hv[0], ww); ffma2(a1, hv[1], ww); ffma2(a2, hv[2], ww);
        ffma2(a3, hv[3], ww); ffma2(a4, hv[4], ww);
      }
    }
    float bb = b_bg[hh*64 + d];
    float lo, hi;
    float* o = g_kk + (size_t)tb*2560 + (size_t)hh*10*64 + d;
    unpack2(a0, lo, hi); o[0*64]=bb+lo; o[1*64]=bb+hi;
    unpack2(a1, lo, hi); o[2*64]=bb+lo; o[3*64]=bb+hi;
    unpack2(a2, lo, hi); o[4*64]=bb+lo; o[5*64]=bb+hi;
    unpack2(a3, lo, hi); o[6*64]=bb+lo; o[7*64]=bb+hi;
    unpack2(a4, lo, hi); o[8*64]=bb+lo; o[9*64]=bb+hi;
  }
}

// ================= K2: v + qv =================
__global__ void __launch_bounds__(128,8) k2_kernel(
  const int* __restrict__ prob_id, const int* __restrict__ skills,
  const float* __restrict__ concept_emb, const float* __restrict__ prob_emb,
  const float* __restrict__ W_batch, const float* __restrict__ b_batch)
{
  __shared__ __align__(16) float v[128];
  const int tb = blockIdx.x;
  const int t = tb / B_, b = tb - t*B_;
  const int tid = threadIdx.x;

  float val;
  if (tid < D_){
    float s = 0.f; int cnt = 0;
    #pragma unroll
    for (int c = 0; c < C_; ++c){
      int k = skills[(t*B_ + b)*C_ + c];
      if (k > 0){ s += concept_emb[(size_t)(k-1)*D_ + tid]; cnt++; }
    }
    val = s / (cnt ? (float)cnt : 1.f);
  } else {
    int pid = prob_id[t*B_ + b];
    val = (pid > 0) ? prob_emb[(size_t)(pid-1)*D_ + (tid - D_)] : 0.f;
  }
  v[tid] = val;
  g_v[((size_t)b*(T_+1) + t + 1)*128 + tid] = val;
  if (t == 0) g_v[((size_t)b*(T_+1))*128 + tid] = 0.f;
  __syncthreads();

  int hh = tid >> 5, dp = tid & 31;
  const ull* Wb = reinterpret_cast<const ull*>(W_batch + (size_t)hh*(3*D_*D_)) + dp;
  ull acc = 0;
  const float4* xv = reinterpret_cast<const float4*>(v);
  #pragma unroll 2
  for (int k4 = 0; k4 < 32; ++k4){
    float4 x = xv[k4]; int k = 64 + k4*4;
    ull w0 = Wb[(size_t)(k+0)*32], w1 = Wb[(size_t)(k+1)*32];
    ull w2 = Wb[(size_t)(k+2)*32], w3 = Wb[(size_t)(k+3)*32];
    ffma2(acc, pack2(x.x,x.x), w0); ffma2(acc, pack2(x.y,x.y), w1);
    ffma2(acc, pack2(x.z,x.z), w2); ffma2(acc, pack2(x.w,x.w), w3);
  }
  float lo, hi; unpack2(acc, lo, hi);
  g_qv[(size_t)tb*256 + hh*64 + 2*dp]     = b_batch[hh*64 + 2*dp]     + lo;
  g_qv[(size_t)tb*256 + hh*64 + 2*dp + 1] = b_batch[hh*64 + 2*dp + 1] + hi;
}

// ================= K3: history softmax weights =================
__global__ void __launch_bounds__(512,1) k3_kernel(const int* __restrict__ response)
{
  extern __shared__ float k3s[];
  float* vv   = k3s;
  float* resp = k3s + (T_+1)*129;
  const int b   = blockIdx.x;
  const int tid = threadIdx.x;
  const int lane = tid & 31, wid = tid >> 5;
  const float inv_s128 = 1.0f/sqrtf(128.0f);

  for (int i = tid; i < (T_+1)*128; i += 512){
    int row = i >> 7, col = i & 127;
    vv[row*129 + col] = g_v[(size_t)b*(T_+1)*128 + i];
  }
  for (int j = tid; j <= T_; j += 512)
    resp[j] = (j == 0) ? 0.f : (float)response[(j-1)*B_ + b];
  __syncthreads();

  for (int t = wid; t < T_; t += 16){
    const float* vt = vv + (t+1)*129;
    float scv[4]; int nj = 0;
    for (int j = lane; j <= t; j += 32){
      const float* vj = vv + j*129;
      float a = 0.f;
      #pragma unroll 4
      for (int k = 0; k < 128; ++k) a += vt[k]*vj[k];
      scv[nj++] = a * inv_s128;
    }
    float mx = -1e30f;
    for (int i = 0; i < nj; ++i) mx = fmaxf(mx, scv[i]);
    #pragma unroll
    for (int o = 16; o; o >>= 1) mx = fmaxf(mx, __shfl_xor_sync(0xffffffffu, mx, o));
    float sum = 0.f;
    for (int i = 0; i < nj; ++i){ scv[i] = expf(scv[i]-mx); sum += scv[i]; }
    #pragma unroll
    for (int o = 16; o; o >>= 1) sum += __shfl_xor_sync(0xffffffffu, sum, o);
    float inv = 1.f/sum;
    int i = 0;
    for (int j = lane; j <= t; j += 32, ++i){
      float p = scv[i]*inv;
      float rb = resp[j];
      g_pr[((size_t)b*T_ + t)*132 + j] = p*rb;
      g_pn[((size_t)b*T_ + t)*132 + j] = p*(1.f-rb);
    }
  }
}

// ================= K4: sequential recurrence, NT=1024 =================
struct __align__(16) SmemSeq {
  alignas(16) float part[4096];     // phase-local partials (reused)
  alignas(16) float partV[1024];    // inmap v_resp partials (survive P5b/P6)
  alignas(16) float h[D_];
  alignas(16) float q[256];
  alignas(16) float his_atts[128];
  alignas(16) float hisP[384];
  alignas(16) float bg_atts[384];
  alignas(16) float x10[640];
  alignas(16) float gru_in[256];
  alignas(16) float gx[192];
  alignas(16) float gh[192];
  alignas(16) float hbuf[(T_+1)*D_];
  alignas(16) float kk[2][2560];
  alignas(16) float hvT[2][2304];
  alignas(16) float v[2][128];
  alignas(16) float qv[2][256];
  alignas(16) float pr[2][132];
  alignas(16) float pn[2][132];
  alignas(16) float bgr[2][12];
  float logit[40], att[40], ws[12];
  float pred_vh;
  float dw0, dw1;
};

__device__ __forceinline__ void do_prefetch(SmemSeq* sm, int b, int tn, int nb,
                                            int idx, int nthr)
{
  size_t tb = (size_t)tn*B_ + b;
  float* d0 = sm->kk[nb];  const float* s0 = g_kk + tb*2560;
  float* d1 = sm->hvT[nb]; const float* s1 = g_hv + tb*2304;
  float* d2 = sm->v[nb];   const float* s2 = g_v  + ((size_t)b*(T_+1) + tn + 1)*128;
  float* d3 = sm->qv[nb];  const float* s3 = g_qv + tb*256;
  float* d4 = sm->pr[nb];  const float* s4 = g_pr + ((size_t)b*T_ + tn)*132;
  float* d5 = sm->pn[nb];  const float* s5 = g_pn + ((size_t)b*T_ + tn)*132;
  float* d6 = sm->bgr[nb]; const float* s6 = g_bgr + tb*12;
  for (int u = idx; u < 640; u += nthr) cp16(d0+4*u, s0+4*u);
  for (int u = idx; u < 576; u += nthr) cp16(d1+4*u, s1+4*u);
  for (int u = idx; u <  32; u += nthr) cp16(d2+4*u, s2+4*u);
  for (int u = idx; u <  64; u += nthr) cp16(d3+4*u, s3+4*u);
  for (int u = idx; u <  33; u += nthr) cp16(d4+4*u, s4+4*u);
  for (int u = idx; u <  33; u += nthr) cp16(d5+4*u, s5+4*u);
  for (int u = idx; u <   3; u += nthr) cp16(d6+4*u, s6+4*u);
}

// one k-segment of a GEMV: 4 outputs/thread via LDG.128 (ulonglong2)
__device__ __forceinline__ void gemv_seg(const float* __restrict__ W, int rowlen4, // row length in ull2 units
                                         const float* __restrict__ x, int k0, int nk,
                                         int u, float* __restrict__ outp)
{
  const ulonglong2* Wp = reinterpret_cast<const ulonglong2*>(W) + (size_t)k0*rowlen4 + u;
  ull a0 = 0, a1 = 0;
  #pragma unroll 4
  for (int k = 0; k < nk; ++k){
    float xk = x[k0 + k];
    ulonglong2 w = Wp[(size_t)k*rowlen4];
    ull xx = pack2(xk, xk);
    ffma2(a0, xx, w.x);
    ffma2(a1, xx, w.y);
  }
  float l0,h0,l1,h1; unpack2(a0,l0,h0); unpack2(a1,l1,h1);
  *reinterpret_cast<float4*>(outp) = make_float4(l0,h0,l1,h1);
}

__global__ void __launch_bounds__(NT,1) k4_kernel(
  const int* __restrict__ response,
  const float* __restrict__ W_pred, const float* __restrict__ b_pred,
  const float* __restrict__ W_ih, const float* __restrict__ W_hh,
  const float* __restrict__ b_ih, const float* __restrict__ b_hh,
  const float* __restrict__ W_batch,
  const float* __restrict__ W_bgint, const float* __restrict__ b_bgint,
  const float* __restrict__ W_hisint, const float* __restrict__ b_hisint,
  const float* __restrict__ W_inmap, const float* __restrict__ b_inmap,
  const float* __restrict__ dir_w, const float* __restrict__ heads_map,
  float* __restrict__ out)
{
  extern __shared__ unsigned char smraw[];
  SmemSeq* sm = reinterpret_cast<SmemSeq*>(smraw);
  const int b    = blockIdx.x;
  const int tid  = threadIdx.x;
  const int lane = tid & 31;
  const int wid  = tid >> 5;
  const float inv_s192 = 1.0f/sqrtf(192.0f);

  if (tid < D_){ sm->h[tid] = 0.f; sm->hbuf[tid] = 0.f; }
  if (tid == NT-1){
    float w0 = dir_w[0], w1 = dir_w[1];
    float m  = fmaxf(w0, w1);
    float e0 = expf(w0 - m), e1 = expf(w1 - m);
    sm->dw0 = e0/(e0+e1); sm->dw1 = e1/(e0+e1);
  }
  do_prefetch(sm, b, 0, 0, tid, NT);
  asm volatile("cp.async.commit_group;");
  __syncthreads();

  for (int t = 0; t < T_; ++t){
    const int cur = t & 1, nxt = cur ^ 1;
    asm volatile("cp.async.wait_group 0;");
    __syncthreads();

    // ===== P0: q h-part (0..127) | his_atts (128..255) | v_resp (256..383) | prefetch (384..1023) =====
    if (tid < 128){
      int seg = tid >> 6, u = tid & 63;          // u = (h, d4): h=u>>4, d4=u&15
      int hh = u >> 4, d4 = u & 15;
      gemv_seg(W_batch + (size_t)hh*(192*64), 16, sm->h, seg*32, 32, d4,
               &sm->part[1920 + seg*256 + 4*u]);
    } else if (tid < 256){
      int u = tid - 128, d = u & 63;
      const float* w = (u < 64) ? sm->pr[cur] : sm->pn[cur];
      const float* hb = sm->hbuf;
      float a0 = 0.f, a1 = 0.f;
      int j = 0;
      for (; j + 1 <= t; j += 2){
        a0 += w[j]  *hb[j*D_ + d];
        a1 += w[j+1]*hb[(j+1)*D_ + d];
      }
      if (j <= t) a0 += w[j]*hb[j*D_ + d];
      sm->his_atts[u] = a0 + a1;
    } else if (tid < 384){
      int u = tid - 256;
      float rf = (float)response[t*B_ + b];
      float vv = sm->v[cur][u];
      sm->x10[384 + u] = vv*rf;
      sm->x10[512 + u] = vv*(1.f - rf);
    } else {
      if (t + 1 < T_){
        do_prefetch(sm, b, t+1, nxt, tid-384, 640);
        asm volatile("cp.async.commit_group;");
      }
    }
    __syncthreads();

    // ===== P1: q combine (0..255) | W_hisint (256..639) | W_hh (640..735) | pred_vh (736..767) =====
    if (tid < 256){
      sm->q[tid] = sm->qv[cur][tid] + sm->part[1920 + tid] + sm->part[1920 + 256 + tid];
    } else if (tid < 640){
      int i = tid - 256, seg = i / 96, u = i - seg*96;  // 4 segs x 32k
      gemv_seg(W_hisint, 96, sm->his_atts, seg*32, 32, u, &sm->part[seg*384 + 4*u]);
    } else if (tid < 736){
      int i = tid - 640, seg = i / 48, u = i - seg*48;  // 2 segs x 32k
      gemv_seg(W_hh, 48, sm->h, seg*32, 32, u, &sm->part[1536 + seg*192 + 4*u]);
    } else if (tid < 768){
      int l = tid - 736;
      float part = 0.f;
      #pragma unroll
      for (int it = 0; it < 6; ++it){
        int i = 384 + it*32 + l;
        float xv = (i < 512) ? sm->v[cur][i - 384] : sm->h[i - 512];
        part += xv * W_pred[i];
      }
      #pragma unroll
      for (int o = 16; o; o >>= 1) part += __shfl_xor_sync(0xffffffffu, part, o);
      if (l == 0) sm->pred_vh = part;
    }
    __syncthreads();

    // ===== P2: logits (warps 0..7) | hisP combine (256..639) | gh combine (640..831) =====
    if (wid < 8){
      for (int p = wid; p < 40; p += 8){
        int hh = p / 10;
        float a = sm->kk[cur][p*64 + lane]      * sm->q[hh*64 + lane]
                + sm->kk[cur][p*64 + 32 + lane] * sm->q[hh*64 + 32 + lane];
        #pragma unroll
        for (int o = 16; o; o >>= 1) a += __shfl_xor_sync(0xffffffffu, a, o);
        if (lane == 0) sm->logit[p] = a * inv_s192;
      }
    } else if (tid >= 256 && tid < 640){
      int j = tid - 256;
      sm->hisP[j] = b_hisint[j] + sm->part[j] + sm->part[384 + j]
                  + sm->part[768 + j] + sm->part[1152 + j];
    } else if (tid >= 640 && tid < 832){
      int j = tid - 640;
      sm->gh[j] = b_hh[j] + sm->part[1536 + j] + sm->part[1536 + 192 + j];
    }
    __syncthreads();

    // ===== P3: att softmax + ws (warp 0) =====
    if (wid == 0){
      if (lane < H_){
        float mx = -1e30f;
        #pragma unroll
        for (int s = 0; s < SEE_; ++s) mx = fmaxf(mx, sm->logit[lane*10 + s]);
        float sum = 0.f;
        #pragma unroll
        for (int s = 0; s < SEE_; ++s){
          float e = expf(sm->logit[lane*10 + s] - mx);
          sm->att[lane*10 + s] = e; sum += e;
        }
        float inv = 1.f/sum;
        #pragma unroll
        for (int s = 0; s < SEE_; ++s) sm->att[lane*10 + s] *= inv;
      }
      __syncwarp();
      if (lane < SEE_){
        float a = 0.f;
        #pragma unroll
        for (int hh = 0; hh < H_; ++hh) a += heads_map[hh]*sm->att[hh*10 + lane];
        sm->ws[lane] = a;
      }
    }
    __syncthreads();

    // ===== P4: bg_atts (0..383) =====
    if (tid < 384){
      bool lo_ = tid < 192;
      int kidx = lo_ ? tid : tid - 192;
      float acc = 0.f;
      #pragma unroll
      for (int s = 0; s < SEE_; ++s){
        float r = sm->bgr[cur][s];
        acc += sm->ws[s] * sm->hvT[cur][kidx*12 + s] * (lo_ ? r : (1.f - r));
      }
      sm->bg_atts[tid] = acc;
    }
    __syncthreads();

    // ===== P5: W_bgint (0..767, 8 segs x 48k) | W_inmap v_resp part (768..1023, 4 segs x 64k) =====
    if (tid < 768){
      int seg = tid / 96, u = tid - seg*96;
      gemv_seg(W_bgint, 96, sm->bg_atts, seg*48, 48, u, &sm->part[seg*384 + 4*u]);
    } else {
      int i = tid - 768, seg = i >> 6, u = i & 63;
      gemv_seg(W_inmap, 64, sm->x10, 384 + seg*64, 64, u, &sm->partV[seg*256 + 4*u]);
    }
    __syncthreads();

    // ===== P5b: x10 peer combine (0..383) =====
    if (tid < 384){
      float s8 = 0.f;
      #pragma unroll
      for (int s = 0; s < 8; ++s) s8 += sm->part[s*384 + tid];
      sm->x10[tid] = sm->dw0*(s8 + b_bgint[tid]) + sm->dw1*sm->hisP[tid];
    }
    __syncthreads();

    // ===== P6: W_inmap peer part (all 1024, 16 segs x 24k) =====
    {
      int seg = tid >> 6, u = tid & 63;
      gemv_seg(W_inmap, 64, sm->x10, seg*24, 24, u, &sm->part[seg*256 + 4*u]);
    }
    __syncthreads();

    // ===== P6b: gru_in combine (0..255) =====
    if (tid < 256){
      float a = b_inmap[tid];
      #pragma unroll
      for (int s = 0; s < 16; ++s) a += sm->part[s*256 + tid];
      #pragma unroll
      for (int s = 0; s < 4; ++s)  a += sm->partV[s*256 + tid];
      sm->gru_in[tid] = a;
    }
    __syncthreads();

    // ===== P7: W_ih (0..767, 16 segs x 16k) | pred peer + out (768..799) =====
    if (tid < 768){
      int seg = tid / 48, u = tid - seg*48;
      gemv_seg(W_ih, 48, sm->gru_in, seg*16, 16, u, &sm->part[seg*192 + 4*u]);
    } else if (tid < 800){
      int l = tid - 768;
      float part = 0.f;
      #pragma unroll
      for (int it = 0; it < 12; ++it){
        int i = it*32 + l;
        part += sm->x10[i] * W_pred[i];
      }
      #pragma unroll
      for (int o = 16; o; o >>= 1) part += __shfl_xor_sync(0xffffffffu, part, o);
      if (l == 0) out[b*T_ + t] = part + sm->pred_vh + b_pred[0];
    }
    __syncthreads();

    // ===== P7b: gx combine (0..191) =====
    if (tid < 192){
      float a = b_ih[tid];
      #pragma unroll
      for (int s = 0; s < 16; ++s) a += sm->part[s*192 + tid];
      sm->gx[tid] = a;
    }
    __syncthreads();

    // ===== P8: GRU update =====
    if (tid < D_){
      float r  = sigmoidf_(sm->gx[tid]        + sm->gh[tid]);
      float z  = sigmoidf_(sm->gx[D_   + tid] + sm->gh[D_   + tid]);
      float n  = tanhf   (sm->gx[2*D_ + tid]  + r*sm->gh[2*D_ + tid]);
      float nh = (1.f - z)*n + z*sm->h[tid];
      sm->h[tid] = nh;
      sm->hbuf[(size_t)(t+1)*D_ + tid] = nh;
    }
    __syncthreads();
  }
}

extern "C" void kernel_launch(void* const* d_in, const int* in_sizes, int n_in,
                              void* d_out, int out_size)
{
  (void)in_sizes; (void)n_in; (void)out_size;

  const int*   prob_id      = (const int*)  d_in[0];
  const int*   skills       = (const int*)  d_in[1];
  const int*   response     = (const int*)  d_in[2];
  const int*   bg_index     = (const int*)  d_in[3];
  const int*   mem_prob_ids = (const int*)  d_in[4];
  const int*   mem_resp     = (const int*)  d_in[5];
  const int*   mem_concepts = (const int*)  d_in[6];
  const float* states_mem   = (const float*)d_in[7];
  const float* concept_emb  = (const float*)d_in[8];
  const float* prob_emb     = (const float*)d_in[9];
  const float* W_pred       = (const float*)d_in[10];
  const float* b_pred       = (const float*)d_in[11];
  const float* W_ih         = (const float*)d_in[12];
  const float* W_hh         = (const float*)d_in[13];
  const float* b_ih         = (const float*)d_in[14];
  const float* b_hh         = (const float*)d_in[15];
  const float* W_batch      = (const float*)d_in[16];
  const float* b_batch      = (const float*)d_in[17];
  const float* W_bg         = (const float*)d_in[18];
  const float* b_bg         = (const float*)d_in[19];
  const float* W_bgint      = (const float*)d_in[20];
  const float* b_bgint      = (const float*)d_in[21];
  const float* W_hisint     = (const float*)d_in[22];
  const float* b_hisint     = (const float*)d_in[23];
  const float* W_inmap      = (const float*)d_in[24];
  const float* b_inmap      = (const float*)d_in[25];
  const float* dir_w        = (const float*)d_in[26];
  const float* heads_map    = (const float*)d_in[27];

  k1_kernel<<<T_*B_, 256>>>(bg_index, mem_prob_ids, mem_resp, mem_concepts,
                            states_mem, concept_emb, prob_emb, W_bg, b_bg);
  k2_kernel<<<T_*B_, 128>>>(prob_id, skills, concept_emb, prob_emb, W_batch, b_batch);

  int k3smem = ((T_+1)*129 + 132) * (int)sizeof(float);
  cudaFuncSetAttribute(k3_kernel, cudaFuncAttributeMaxDynamicSharedMemorySize, k3smem);
  k3_kernel<<<B_, 512, k3smem>>>(response);

  cudaFuncSetAttribute(k4_kernel, cudaFuncAttributeMaxDynamicSharedMemorySize,
                       (int)sizeof(SmemSeq));
  k4_kernel<<<B_, NT, sizeof(SmemSeq)>>>(
    response, W_pred, b_pred, W_ih, W_hh, b_ih, b_hh, W_batch,
    W_bgint, b_bgint, W_hisint, b_hisint, W_inmap, b_inmap,
    dir_w, heads_map, (float*)d_out);
}

// round 15
// speedup vs baseline: 1.6066x; 1.1556x over previous
#include <cuda_runtime.h>
#include <math.h>

#define D_   64
#define T_   128
#define B_   64
#define R_   20
#define SEE_ 10
#define H_   4
#define C_   4
#define NT   1024

typedef unsigned long long ull;

// ---------------- precomputed per-(t,b) data ----------------
__device__ __align__(16) float g_kk [ (size_t)B_*T_*2560 ];
__device__ __align__(16) float g_K2 [ (size_t)B_*T_*2560 ];  // [(tb)][p*64+e], p=h*10+s
__device__ __align__(16) float g_pc [ (size_t)B_*T_*40 ];    // qv·kk per (tb,p)
__device__ __align__(16) float g_hv [ (size_t)B_*T_*2304 ];
__device__ __align__(16) float g_bgr[ (size_t)B_*T_*12 ];
__device__ __align__(16) float g_qv [ (size_t)B_*T_*256 ];
__device__ __align__(16) float g_v  [ (size_t)B_*(T_+1)*128 ];
__device__ __align__(16) float g_pr [ (size_t)B_*T_*132 ];
__device__ __align__(16) float g_pn [ (size_t)B_*T_*132 ];
// ---------------- folded weights ----------------
__device__ __align__(16) float g_Mbg [384*256];   // W_bgint @ W_inmap_peer
__device__ __align__(16) float g_Mhis[128*256];   // W_hisint @ W_inmap_peer
__device__ __align__(16) float g_wbgp[384];       // W_bgint @ W_pred[:384]
__device__ __align__(16) float g_whp [128];       // W_hisint @ W_pred[:384]
__device__ __align__(16) float g_vb1 [256];       // b_bgint @ W_inmap_peer
__device__ __align__(16) float g_vb2 [256];       // b_hisint @ W_inmap_peer
__device__            float g_sb  [2];            // b_bgint·Wp, b_hisint·Wp

// ---------------- helpers ----------------
__device__ __forceinline__ void ffma2(ull& a, ull x, ull w){
  asm("fma.rn.f32x2 %0, %1, %2, %0;" : "+l"(a) : "l"(x), "l"(w));
}
__device__ __forceinline__ ull pack2(float lo, float hi){
  ull r; asm("mov.b64 %0, {%1,%2};" : "=l"(r) : "f"(lo), "f"(hi)); return r;
}
__device__ __forceinline__ void unpack2(ull a, float& lo, float& hi){
  asm("mov.b64 {%0,%1}, %2;" : "=f"(lo), "=f"(hi) : "l"(a));
}
__device__ __forceinline__ float sigmoidf_(float x){ return 1.0f/(1.0f+expf(-x)); }
__device__ __forceinline__ void cp16(void* sdst, const void* gsrc){
  unsigned sa;
  asm("{.reg .u64 t; cvta.to.shared.u64 t, %1; cvt.u32.u64 %0, t;}" : "=r"(sa) : "l"(sdst));
  asm volatile("cp.async.cg.shared.global [%0], [%1], 16;" :: "r"(sa), "l"(gsrc));
}

// ================= K1: bg gather + kk GEMV (unchanged) =================
__global__ void __launch_bounds__(256,4) k1_kernel(
  const int* __restrict__ bg_index, const int* __restrict__ mem_prob_ids,
  const int* __restrict__ mem_resp, const int* __restrict__ mem_concepts,
  const float* __restrict__ states_mem, const float* __restrict__ concept_emb,
  const float* __restrict__ prob_emb,
  const float* __restrict__ W_bg, const float* __restrict__ b_bg)
{
  __shared__ __align__(16) float hvT[2304];
  const int tb = blockIdx.x;
  const int t = tb / B_, b = tb - t*B_;
  const int tid = threadIdx.x;

  for (int i = tid; i < 192*2; i += 256) hvT[(i>>1)*12 + 10 + (i&1)] = 0.f;
  for (int i = tid; i < SEE_*3*D_; i += 256){
    int s = i / (3*D_);
    int k = i - s*3*D_;
    int idx = bg_index[(t*B_ + b)*R_ + s];
    float val;
    if (k < D_){
      val = states_mem[(size_t)idx*D_ + k];
    } else if (k < 2*D_){
      int d = k - D_;
      float ss = 0.f; int cnt = 0;
      #pragma unroll
      for (int c = 0; c < C_; ++c){
        int kc = mem_concepts[(size_t)idx*C_ + c];
        if (kc > 0){ ss += concept_emb[(size_t)(kc-1)*D_ + d]; cnt++; }
      }
      val = ss / (cnt ? (float)cnt : 1.f);
    } else {
      int d  = k - 2*D_;
      int mp = mem_prob_ids[idx];
      val = (mp > 0) ? prob_emb[(size_t)(mp-1)*D_ + d] : 0.f;
    }
    hvT[k*12 + s] = val;
  }
  if (tid < SEE_){
    int idx = bg_index[(t*B_ + b)*R_ + tid];
    g_bgr[(size_t)tb*12 + tid] = (float)mem_resp[idx];
  }
  __syncthreads();

  for (int i = tid; i < 2304; i += 256)
    g_hv[(size_t)tb*2304 + i] = hvT[i];

  {
    int hh = tid >> 6, d = tid & 63;
    const float* Wg = W_bg + (size_t)hh*(3*D_*D_) + d;
    ull a0=0,a1=0,a2=0,a3=0,a4=0;
    #pragma unroll 2
    for (int k0 = 0; k0 < 192; k0 += 8){
      float w[8];
      #pragma unroll
      for (int u = 0; u < 8; ++u) w[u] = Wg[(size_t)(k0+u)*64];
      #pragma unroll
      for (int u = 0; u < 8; ++u){
        ull ww = pack2(w[u], w[u]);
        const ull* hv = reinterpret_cast<const ull*>(hvT + (k0+u)*12);
        ffma2(a0, hv[0], ww); ffma2(a1, hv[1], ww); ffma2(a2, hv[2], ww);
        ffma2(a3, hv[3], ww); ffma2(a4, hv[4], ww);
      }
    }
    float bb = b_bg[hh*64 + d];
    float lo, hi;
    float* o = g_kk + (size_t)tb*2560 + (size_t)hh*10*64 + d;
    unpack2(a0, lo, hi); o[0*64]=bb+lo; o[1*64]=bb+hi;
    unpack2(a1, lo, hi); o[2*64]=bb+lo; o[3*64]=bb+hi;
    unpack2(a2, lo, hi); o[4*64]=bb+lo; o[5*64]=bb+hi;
    unpack2(a3, lo, hi); o[6*64]=bb+lo; o[7*64]=bb+hi;
    unpack2(a4, lo, hi); o[8*64]=bb+lo; o[9*64]=bb+hi;
  }
}

// ================= K2: v + qv (unchanged) =================
__global__ void __launch_bounds__(128,8) k2_kernel(
  const int* __restrict__ prob_id, const int* __restrict__ skills,
  const float* __restrict__ concept_emb, const float* __restrict__ prob_emb,
  const float* __restrict__ W_batch, const float* __restrict__ b_batch)
{
  __shared__ __align__(16) float v[128];
  const int tb = blockIdx.x;
  const int t = tb / B_, b = tb - t*B_;
  const int tid = threadIdx.x;

  float val;
  if (tid < D_){
    float s = 0.f; int cnt = 0;
    #pragma unroll
    for (int c = 0; c < C_; ++c){
      int k = skills[(t*B_ + b)*C_ + c];
      if (k > 0){ s += concept_emb[(size_t)(k-1)*D_ + tid]; cnt++; }
    }
    val = s / (cnt ? (float)cnt : 1.f);
  } else {
    int pid = prob_id[t*B_ + b];
    val = (pid > 0) ? prob_emb[(size_t)(pid-1)*D_ + (tid - D_)] : 0.f;
  }
  v[tid] = val;
  g_v[((size_t)b*(T_+1) + t + 1)*128 + tid] = val;
  if (t == 0) g_v[((size_t)b*(T_+1))*128 + tid] = 0.f;
  __syncthreads();

  int hh = tid >> 5, dp = tid & 31;
  const ull* Wb = reinterpret_cast<const ull*>(W_batch + (size_t)hh*(3*D_*D_)) + dp;
  ull acc = 0;
  const float4* xv = reinterpret_cast<const float4*>(v);
  #pragma unroll 2
  for (int k4 = 0; k4 < 32; ++k4){
    float4 x = xv[k4]; int k = 64 + k4*4;
    ull w0 = Wb[(size_t)(k+0)*32], w1 = Wb[(size_t)(k+1)*32];
    ull w2 = Wb[(size_t)(k+2)*32], w3 = Wb[(size_t)(k+3)*32];
    ffma2(acc, pack2(x.x,x.x), w0); ffma2(acc, pack2(x.y,x.y), w1);
    ffma2(acc, pack2(x.z,x.z), w2); ffma2(acc, pack2(x.w,x.w), w3);
  }
  float lo, hi; unpack2(acc, lo, hi);
  g_qv[(size_t)tb*256 + hh*64 + 2*dp]     = b_batch[hh*64 + 2*dp]     + lo;
  g_qv[(size_t)tb*256 + hh*64 + 2*dp + 1] = b_batch[hh*64 + 2*dp + 1] + hi;
}

// ================= foldM: M_bg, M_his =================
__global__ void __launch_bounds__(256,1) foldM_kernel(
  const float* __restrict__ Wbgint, const float* __restrict__ Whisint,
  const float* __restrict__ Winmap)
{
  __shared__ float xs[16*384];
  const int r0 = blockIdx.x*16;      // 32 blocks, rows 0..511 (384 bg + 128 his)
  const int tid = threadIdx.x;
  for (int i = tid; i < 16*384; i += 256){
    int rr = i/384, j = i - rr*384;
    int gi = r0 + rr;
    xs[i] = (gi < 384) ? Wbgint[(size_t)gi*384 + j] : Whisint[(size_t)(gi-384)*384 + j];
  }
  __syncthreads();
  const int m = tid;
  float acc[16];
  #pragma unroll
  for (int rr = 0; rr < 16; ++rr) acc[rr] = 0.f;
  for (int j = 0; j < 384; ++j){
    float w = Winmap[(size_t)j*256 + m];
    #pragma unroll
    for (int rr = 0; rr < 16; ++rr) acc[rr] += xs[rr*384 + j]*w;
  }
  #pragma unroll
  for (int rr = 0; rr < 16; ++rr){
    int gi = r0 + rr;
    if (gi < 384) g_Mbg[(size_t)gi*256 + m] = acc[rr];
    else          g_Mhis[(size_t)(gi-384)*256 + m] = acc[rr];
  }
}

// ================= foldV: vectors/scalars =================
__global__ void __launch_bounds__(1024,1) foldV_kernel(
  const float* __restrict__ Wbgint, const float* __restrict__ Whisint,
  const float* __restrict__ Winmap, const float* __restrict__ Wpred,
  const float* __restrict__ b_bgint, const float* __restrict__ b_hisint)
{
  const int tid = threadIdx.x;
  if (tid < 384){
    float acc = 0.f;
    for (int j = 0; j < 384; ++j) acc += Wbgint[(size_t)tid*384 + j]*Wpred[j];
    g_wbgp[tid] = acc;
    if (tid < 2){
      const float* bb = (tid == 0) ? b_bgint : b_hisint;
      float s = 0.f;
      for (int j = 0; j < 384; ++j) s += bb[j]*Wpred[j];
      g_sb[tid] = s;
    }
  } else if (tid < 512){
    int i = tid - 384; float acc = 0.f;
    for (int j = 0; j < 384; ++j) acc += Whisint[(size_t)i*384 + j]*Wpred[j];
    g_whp[i] = acc;
  } else if (tid < 768){
    int m = tid - 512; float acc = 0.f;
    for (int j = 0; j < 384; ++j) acc += b_bgint[j]*Winmap[(size_t)j*256 + m];
    g_vb1[m] = acc;
  } else {
    int m = tid - 768; float acc = 0.f;
    for (int j = 0; j < 384; ++j) acc += b_hisint[j]*Winmap[(size_t)j*256 + m];
    g_vb2[m] = acc;
  }
}

// ================= kK2: K2[p][e] = sum_d Wb_h[h][e][d]*kk[p][d]; pc = qv·kk =================
__global__ void __launch_bounds__(1024,1) kK2_kernel(const float* __restrict__ W_batch)
{
  extern __shared__ float sK2[];
  float* WbT = sK2;                 // [4][64 d][68 pad] -> WbT[h*4352 + d*68 + e]
  float* kks = sK2 + 4*4352;        // [8 tb][2560]
  const int tid = threadIdx.x;

  for (int i = tid; i < 4*64*64; i += 1024){
    int h = i >> 12, rem = i & 4095, e = rem >> 6, d = rem & 63;
    WbT[h*4352 + d*68 + e] = W_batch[(size_t)h*12288 + e*64 + d];
  }
  for (int i = tid; i < 8*2560; i += 1024){
    int tb = i / 2560, r = i - tb*2560;
    kks[i] = g_kk[((size_t)blockIdx.x*8 + tb)*2560 + r];
  }
  __syncthreads();

  // 1024 tiles: (tb<8, h<4, sg<2, eg<16); 5 p-rows x 4 e-cols each
  {
    int tb = tid >> 7, rem = tid & 127;
    int h = rem >> 5, rem2 = rem & 31;
    int sg = rem2 >> 4, eg = rem2 & 15;
    int p0 = h*10 + sg*5, e0 = eg*4;
    const float* wb = WbT + h*4352 + e0;
    const float* kr = kks + tb*2560 + p0*64;
    float4 acc[5];
    #pragma unroll
    for (int i = 0; i < 5; ++i) acc[i] = make_float4(0.f,0.f,0.f,0.f);
    #pragma unroll 4
    for (int d = 0; d < 64; ++d){
      float4 w = *reinterpret_cast<const float4*>(wb + d*68);
      #pragma unroll
      for (int i = 0; i < 5; ++i){
        float kv = kr[i*64 + d];
        acc[i].x += kv*w.x; acc[i].y += kv*w.y;
        acc[i].z += kv*w.z; acc[i].w += kv*w.w;
      }
    }
    size_t tbg = (size_t)blockIdx.x*8 + tb;
    #pragma unroll
    for (int i = 0; i < 5; ++i)
      *reinterpret_cast<float4*>(g_K2 + tbg*2560 + (p0+i)*64 + e0) = acc[i];
  }
  // pc
  if (tid < 320){
    int tb = tid / 40, p = tid - tb*40, h = p/10;
    size_t tbg = (size_t)blockIdx.x*8 + tb;
    const float* qv = g_qv + tbg*256 + h*64;
    const float* kr = kks + tb*2560 + p*64;
    float acc = 0.f;
    #pragma unroll 4
    for (int d = 0; d < 64; ++d) acc += qv[d]*kr[d];
    g_pc[tbg*40 + p] = acc;
  }
}

// ================= K3: history softmax weights (with zero pads) =================
__global__ void __launch_bounds__(512,1) k3_kernel(const int* __restrict__ response)
{
  extern __shared__ float k3s[];
  float* vv   = k3s;
  float* resp = k3s + (T_+1)*129;
  const int b   = blockIdx.x;
  const int tid = threadIdx.x;
  const int lane = tid & 31, wid = tid >> 5;
  const float inv_s128 = 1.0f/sqrtf(128.0f);

  for (int i = tid; i < (T_+1)*128; i += 512){
    int row = i >> 7, col = i & 127;
    vv[row*129 + col] = g_v[(size_t)b*(T_+1)*128 + i];
  }
  for (int j = tid; j <= T_; j += 512)
    resp[j] = (j == 0) ? 0.f : (float)response[(j-1)*B_ + b];
  __syncthreads();

  for (int t = wid; t < T_; t += 16){
    const float* vt = vv + (t+1)*129;
    float scv[4]; int nj = 0;
    for (int j = lane; j <= t; j += 32){
      const float* vj = vv + j*129;
      float a = 0.f;
      #pragma unroll 4
      for (int k = 0; k < 128; ++k) a += vt[k]*vj[k];
      scv[nj++] = a * inv_s128;
    }
    float mx = -1e30f;
    for (int i = 0; i < nj; ++i) mx = fmaxf(mx, scv[i]);
    #pragma unroll
    for (int o = 16; o; o >>= 1) mx = fmaxf(mx, __shfl_xor_sync(0xffffffffu, mx, o));
    float sum = 0.f;
    for (int i = 0; i < nj; ++i){ scv[i] = expf(scv[i]-mx); sum += scv[i]; }
    #pragma unroll
    for (int o = 16; o; o >>= 1) sum += __shfl_xor_sync(0xffffffffu, sum, o);
    float inv = 1.f/sum;
    int i = 0;
    for (int j = lane; j <= t; j += 32, ++i){
      float p = scv[i]*inv;
      float rb = resp[j];
      g_pr[((size_t)b*T_ + t)*132 + j] = p*rb;
      g_pn[((size_t)b*T_ + t)*132 + j] = p*(1.f-rb);
    }
    for (int j = t+1+lane; j < 132; j += 32){
      g_pr[((size_t)b*T_ + t)*132 + j] = 0.f;
      g_pn[((size_t)b*T_ + t)*132 + j] = 0.f;
    }
  }
}

// ================= K4: sequential recurrence =================
struct __align__(16) SmemSeq {
  alignas(16) float partA[16*256];
  alignas(16) float partB[4*256];
  alignas(16) float partC[8*256];
  alignas(16) float partD[2*192];
  alignas(16) float partE[16*192];
  alignas(16) float h[64];
  alignas(16) float his[128];
  alignas(16) float x10v[256];
  alignas(16) float bg_atts[384];
  alignas(16) float gru_in[256];
  alignas(16) float gh[192];
  alignas(16) float hbufT[64*132];
  alignas(16) float K2s[2][2560];
  alignas(16) float pcs[2][40];
  alignas(16) float hvT[2][2304];
  alignas(16) float v[2][128];
  alignas(16) float pr[2][132];
  alignas(16) float pn[2][132];
  alignas(16) float bgr[2][12];
  float logit[40], att[40], ws[12];
  float pred_vh, pred_his;
  float dw0, dw1;
};

__device__ __forceinline__ void do_prefetch(SmemSeq* sm, int b, int tn, int nb,
                                            int idx, int nthr)
{
  size_t tb = (size_t)tn*B_ + b;
  float* d0 = sm->K2s[nb]; const float* s0 = g_K2 + tb*2560;
  float* d1 = sm->hvT[nb]; const float* s1 = g_hv + tb*2304;
  float* d2 = sm->v[nb];   const float* s2 = g_v  + ((size_t)b*(T_+1) + tn + 1)*128;
  float* d3 = sm->pcs[nb]; const float* s3 = g_pc + tb*40;
  float* d4 = sm->pr[nb];  const float* s4 = g_pr + ((size_t)b*T_ + tn)*132;
  float* d5 = sm->pn[nb];  const float* s5 = g_pn + ((size_t)b*T_ + tn)*132;
  float* d6 = sm->bgr[nb]; const float* s6 = g_bgr + tb*12;
  for (int u = idx; u < 640; u += nthr) cp16(d0+4*u, s0+4*u);
  for (int u = idx; u < 576; u += nthr) cp16(d1+4*u, s1+4*u);
  for (int u = idx; u <  32; u += nthr) cp16(d2+4*u, s2+4*u);
  for (int u = idx; u <  10; u += nthr) cp16(d3+4*u, s3+4*u);
  for (int u = idx; u <  33; u += nthr) cp16(d4+4*u, s4+4*u);
  for (int u = idx; u <  33; u += nthr) cp16(d5+4*u, s5+4*u);
  for (int u = idx; u <   3; u += nthr) cp16(d6+4*u, s6+4*u);
}

__device__ __forceinline__ void gemv_seg(const float* __restrict__ W, int rowlen4,
                                         const float* __restrict__ x, int k0, int nk,
                                         int u, float* __restrict__ outp)
{
  const ulonglong2* Wp = reinterpret_cast<const ulonglong2*>(W) + (size_t)k0*rowlen4 + u;
  ull a0 = 0, a1 = 0;
  #pragma unroll 4
  for (int k = 0; k < nk; ++k){
    float xk = x[k0 + k];
    ulonglong2 w = Wp[(size_t)k*rowlen4];
    ull xx = pack2(xk, xk);
    ffma2(a0, xx, w.x);
    ffma2(a1, xx, w.y);
  }
  float l0,h0,l1,h1; unpack2(a0,l0,h0); unpack2(a1,l1,h1);
  *reinterpret_cast<float4*>(outp) = make_float4(l0,h0,l1,h1);
}

__global__ void __launch_bounds__(NT,1) k4_kernel(
  const int* __restrict__ response,
  const float* __restrict__ W_pred, const float* __restrict__ b_pred,
  const float* __restrict__ W_ih, const float* __restrict__ W_hh,
  const float* __restrict__ b_ih, const float* __restrict__ b_hh,
  const float* __restrict__ W_inmap, const float* __restrict__ b_inmap,
  const float* __restrict__ dir_w, const float* __restrict__ heads_map,
  float* __restrict__ out)
{
  extern __shared__ unsigned char smraw[];
  SmemSeq* sm = reinterpret_cast<SmemSeq*>(smraw);
  const int b    = blockIdx.x;
  const int tid  = threadIdx.x;
  const int lane = tid & 31;
  const int wid  = tid >> 5;
  const float inv_s192 = 1.0f/sqrtf(192.0f);

  if (tid < 64){ sm->h[tid] = 0.f; sm->hbufT[tid*132] = 0.f; }
  if (tid == NT-1){
    float w0 = dir_w[0], w1 = dir_w[1];
    float m  = fmaxf(w0, w1);
    float e0 = expf(w0 - m), e1 = expf(w1 - m);
    sm->dw0 = e0/(e0+e1); sm->dw1 = e1/(e0+e1);
  }
  do_prefetch(sm, b, 0, 0, tid, NT);
  asm volatile("cp.async.commit_group;");
  __syncthreads();

  for (int t = 0; t < T_; ++t){
    const int cur = t & 1, nxt = cur ^ 1;
    asm volatile("cp.async.wait_group 0;");
    __syncthreads();

    // ===== P0: logits (0..639) | his (640..767) | v_resp (768..895) | prefetch (896..1023) =====
    if (tid < 640){
      int p = tid >> 4, l = tid & 15;
      float4 kv = reinterpret_cast<const float4*>(sm->K2s[cur])[p*16 + l];
      float4 hv = reinterpret_cast<const float4*>(sm->h)[l];
      float acc = kv.x*hv.x + kv.y*hv.y + kv.z*hv.z + kv.w*hv.w;
      #pragma unroll
      for (int o = 8; o; o >>= 1) acc += __shfl_xor_sync(0xffffffffu, acc, o);
      if (l == 0) sm->logit[p] = (acc + sm->pcs[cur][p]) * inv_s192;
    } else if (tid < 768){
      int u = tid - 640, d = u & 63;
      const float4* w4 = reinterpret_cast<const float4*>((u < 64) ? sm->pr[cur] : sm->pn[cur]);
      const float4* h4 = reinterpret_cast<const float4*>(sm->hbufT) + d*33;
      float a0 = 0.f, a1 = 0.f;
      int nj4 = (t >> 2) + 1;
      for (int j4 = 0; j4 < nj4; ++j4){
        float4 ww = w4[j4], hh = h4[j4];
        a0 += ww.x*hh.x + ww.y*hh.y;
        a1 += ww.z*hh.z + ww.w*hh.w;
      }
      sm->his[u] = a0 + a1;
    } else if (tid < 896){
      int u = tid - 768;
      float rf = (float)response[t*B_ + b];
      float vv = sm->v[cur][u];
      sm->x10v[u]       = vv*rf;
      sm->x10v[128 + u] = vv*(1.f - rf);
    } else {
      if (t + 1 < T_){
        do_prefetch(sm, b, t+1, nxt, tid-896, 128);
        asm volatile("cp.async.commit_group;");
      }
    }
    __syncthreads();

    // ===== P1: softmax+ws (w0) | pred_vh (w1) | pred_his (w2) | W_hh (96..191) |
    //           M_his (192..447) | inmap_v (448..959) =====
    if (wid == 0){
      if (lane < H_){
        float mx = -1e30f;
        #pragma unroll
        for (int s = 0; s < SEE_; ++s) mx = fmaxf(mx, sm->logit[lane*10 + s]);
        float sum = 0.f;
        #pragma unroll
        for (int s = 0; s < SEE_; ++s){
          float e = expf(sm->logit[lane*10 + s] - mx);
          sm->att[lane*10 + s] = e; sum += e;
        }
        float inv = 1.f/sum;
        #pragma unroll
        for (int s = 0; s < SEE_; ++s) sm->att[lane*10 + s] *= inv;
      }
      __syncwarp();
      if (lane < SEE_){
        float a = 0.f;
        #pragma unroll
        for (int hh = 0; hh < H_; ++hh) a += heads_map[hh]*sm->att[hh*10 + lane];
        sm->ws[lane] = a;
      }
    } else if (wid == 1){
      float part = 0.f;
      #pragma unroll
      for (int it = 0; it < 6; ++it){
        int i = it*32 + lane;
        float xv = (i < 128) ? sm->v[cur][i] : sm->h[i - 128];
        part += xv * W_pred[384 + i];
      }
      #pragma unroll
      for (int o = 16; o; o >>= 1) part += __shfl_xor_sync(0xffffffffu, part, o);
      if (lane == 0) sm->pred_vh = part;
    } else if (wid == 2){
      float part = 0.f;
      #pragma unroll
      for (int j = 0; j < 4; ++j){
        int i = j*32 + lane;
        part += sm->his[i] * g_whp[i];
      }
      #pragma unroll
      for (int o = 16; o; o >>= 1) part += __shfl_xor_sync(0xffffffffu, part, o);
      if (lane == 0) sm->pred_his = part;
    } else if (tid >= 96 && tid < 192){
      int i = tid - 96, seg = i / 48, u = i - seg*48;
      gemv_seg(W_hh, 48, sm->h, seg*32, 32, u, &sm->partD[seg*192 + 4*u]);
    } else if (tid >= 192 && tid < 448){
      int i = tid - 192, seg = i >> 6, u = i & 63;
      gemv_seg(g_Mhis, 64, sm->his, seg*32, 32, u, &sm->partB[seg*256 + 4*u]);
    } else if (tid >= 448 && tid < 960){
      int i = tid - 448, seg = i >> 6, u = i & 63;
      gemv_seg(W_inmap + 384*256, 64, sm->x10v, seg*32, 32, u, &sm->partC[seg*256 + 4*u]);
    }
    __syncthreads();

    // ===== P2: bg_atts (0..383) | gh combine (384..575) =====
    if (tid < 384){
      bool lo_ = tid < 192;
      int kidx = lo_ ? tid : tid - 192;
      float acc = 0.f;
      #pragma unroll
      for (int s = 0; s < SEE_; ++s){
        float r = sm->bgr[cur][s];
        acc += sm->ws[s] * sm->hvT[cur][kidx*12 + s] * (lo_ ? r : (1.f - r));
      }
      sm->bg_atts[tid] = acc;
    } else if (tid < 576){
      int j = tid - 384;
      sm->gh[j] = b_hh[j] + sm->partD[j] + sm->partD[192 + j];
    }
    __syncthreads();

    // ===== P3: M_bg GEMV (all 1024, 16 segs x 24k) =====
    {
      int seg = tid >> 6, u = tid & 63;
      gemv_seg(g_Mbg, 64, sm->bg_atts, seg*24, 24, u, &sm->partA[seg*256 + 4*u]);
    }
    __syncthreads();

    // ===== P4: gru_in combine (0..255) | pred final (256..287) =====
    if (tid < 256){
      float sA = 0.f, sB = 0.f, sC = 0.f;
      #pragma unroll
      for (int s = 0; s < 16; ++s) sA += sm->partA[s*256 + tid];
      #pragma unroll
      for (int s = 0; s < 4; ++s)  sB += sm->partB[s*256 + tid];
      #pragma unroll
      for (int s = 0; s < 8; ++s)  sC += sm->partC[s*256 + tid];
      sm->gru_in[tid] = sm->dw0*(sA + g_vb1[tid]) + sm->dw1*(sB + g_vb2[tid])
                      + sC + b_inmap[tid];
    } else if (tid < 288){
      float part = 0.f;
      #pragma unroll
      for (int j = 0; j < 12; ++j){
        int i = j*32 + lane;
        part += sm->bg_atts[i] * g_wbgp[i];
      }
      #pragma unroll
      for (int o = 16; o; o >>= 1) part += __shfl_xor_sync(0xffffffffu, part, o);
      if (lane == 0)
        out[b*T_ + t] = b_pred[0] + sm->pred_vh
                      + sm->dw0*(part + g_sb[0]) + sm->dw1*(sm->pred_his + g_sb[1]);
    }
    __syncthreads();

    // ===== P5: W_ih (0..767, 16 segs x 16k) =====
    if (tid < 768){
      int seg = tid / 48, u = tid - seg*48;
      gemv_seg(W_ih, 48, sm->gru_in, seg*16, 16, u, &sm->partE[seg*192 + 4*u]);
    }
    __syncthreads();

    // ===== P6: gx combine + GRU update (0..63) =====
    if (tid < 64){
      int d = tid;
      float gr = b_ih[d], gz = b_ih[64+d], gn = b_ih[128+d];
      #pragma unroll
      for (int s = 0; s < 16; ++s){
        const float* pe = sm->partE + s*192;
        gr += pe[d]; gz += pe[64+d]; gn += pe[128+d];
      }
      float r  = sigmoidf_(gr + sm->gh[d]);
      float z  = sigmoidf_(gz + sm->gh[64+d]);
      float n  = tanhf   (gn + r*sm->gh[128+d]);
      float nh = (1.f - z)*n + z*sm->h[d];
      sm->h[d] = nh;
      sm->hbufT[d*132 + (t+1)] = nh;
    }
    __syncthreads();
  }
}

extern "C" void kernel_launch(void* const* d_in, const int* in_sizes, int n_in,
                              void* d_out, int out_size)
{
  (void)in_sizes; (void)n_in; (void)out_size;

  const int*   prob_id      = (const int*)  d_in[0];
  const int*   skills       = (const int*)  d_in[1];
  const int*   response     = (const int*)  d_in[2];
  const int*   bg_index     = (const int*)  d_in[3];
  const int*   mem_prob_ids = (const int*)  d_in[4];
  const int*   mem_resp     = (const int*)  d_in[5];
  const int*   mem_concepts = (const int*)  d_in[6];
  const float* states_mem   = (const float*)d_in[7];
  const float* concept_emb  = (const float*)d_in[8];
  const float* prob_emb     = (const float*)d_in[9];
  const float* W_pred       = (const float*)d_in[10];
  const float* b_pred       = (const float*)d_in[11];
  const float* W_ih         = (const float*)d_in[12];
  const float* W_hh         = (const float*)d_in[13];
  const float* b_ih         = (const float*)d_in[14];
  const float* b_hh         = (const float*)d_in[15];
  const float* W_batch      = (const float*)d_in[16];
  const float* b_batch      = (const float*)d_in[17];
  const float* W_bg         = (const float*)d_in[18];
  const float* b_bg         = (const float*)d_in[19];
  const float* W_bgint      = (const float*)d_in[20];
  const float* b_bgint      = (const float*)d_in[21];
  const float* W_hisint     = (const float*)d_in[22];
  const float* b_hisint     = (const float*)d_in[23];
  const float* W_inmap      = (const float*)d_in[24];
  const float* b_inmap      = (const float*)d_in[25];
  const float* dir_w        = (const float*)d_in[26];
  const float* heads_map    = (const float*)d_in[27];

  k1_kernel<<<T_*B_, 256>>>(bg_index, mem_prob_ids, mem_resp, mem_concepts,
                            states_mem, concept_emb, prob_emb, W_bg, b_bg);
  k2_kernel<<<T_*B_, 128>>>(prob_id, skills, concept_emb, prob_emb, W_batch, b_batch);
  foldM_kernel<<<32, 256>>>(W_bgint, W_hisint, W_inmap);
  foldV_kernel<<<1, 1024>>>(W_bgint, W_hisint, W_inmap, W_pred, b_bgint, b_hisint);

  int kK2smem = (4*4352 + 8*2560) * (int)sizeof(float);
  cudaFuncSetAttribute(kK2_kernel, cudaFuncAttributeMaxDynamicSharedMemorySize, kK2smem);
  kK2_kernel<<<T_*B_/8, 1024, kK2smem>>>(W_batch);

  int k3smem = ((T_+1)*129 + 132) * (int)sizeof(float);
  cudaFuncSetAttribute(k3_kernel, cudaFuncAttributeMaxDynamicSharedMemorySize, k3smem);
  k3_kernel<<<B_, 512, k3smem>>>(response);

  cudaFuncSetAttribute(k4_kernel, cudaFuncAttributeMaxDynamicSharedMemorySize,
                       (int)sizeof(SmemSeq));
  k4_kernel<<<B_, NT, sizeof(SmemSeq)>>>(
    response, W_pred, b_pred, W_ih, W_hh, b_ih, b_hh,
    W_inmap, b_inmap, dir_w, heads_map, (float*)d_out);
}

// round 16
// speedup vs baseline: 2.1345x; 1.3286x over previous
#include <cuda_runtime.h>
#include <math.h>

#define D_   64
#define T_   128
#define B_   64
#define R_   20
#define SEE_ 10
#define H_   4
#define C_   4
#define NT   1024

typedef unsigned long long ull;

// ---------------- precomputed per-(t,b) data ----------------
__device__ __align__(16) float g_kk [ (size_t)B_*T_*2560 ];
__device__ __align__(16) float g_K2 [ (size_t)B_*T_*2560 ];
__device__ __align__(16) float g_pc [ (size_t)B_*T_*40 ];
__device__ __align__(16) float g_hv [ (size_t)B_*T_*2304 ];
__device__ __align__(16) float g_bgr[ (size_t)B_*T_*12 ];
__device__ __align__(16) float g_qv [ (size_t)B_*T_*256 ];
__device__ __align__(16) float g_v  [ (size_t)B_*(T_+1)*128 ];
__device__ __align__(16) float g_pr [ (size_t)B_*T_*132 ];
__device__ __align__(16) float g_pn [ (size_t)B_*T_*132 ];
__device__ __align__(16) float g_gxv[ (size_t)B_*T_*192 ];   // v_resp folded into gx
__device__ __align__(16) float g_pv [ (size_t)B_*T_*4 ];     // v-part of pred (padded)
// ---------------- folded weights ----------------
__device__ __align__(16) float g_Mbg [384*256];
__device__ __align__(16) float g_Mhis[128*256];
__device__ __align__(16) float g_Nbg [384*192];   // M_bg @ W_ih
__device__ __align__(16) float g_Nhis[128*192];   // M_his @ W_ih
__device__ __align__(16) float g_Nv  [256*192];   // W_inmap_v @ W_ih
__device__ __align__(16) float g_gxc [192];       // (dw0*vb1+dw1*vb2+b_inmap)@W_ih + b_ih
__device__ __align__(16) float g_wbgp[384];
__device__ __align__(16) float g_whp [128];
__device__ __align__(16) float g_vb1 [256];
__device__ __align__(16) float g_vb2 [256];
__device__            float g_sb  [2];
__device__            float g_dw  [2];

// ---------------- helpers ----------------
__device__ __forceinline__ void ffma2(ull& a, ull x, ull w){
  asm("fma.rn.f32x2 %0, %1, %2, %0;" : "+l"(a) : "l"(x), "l"(w));
}
__device__ __forceinline__ ull pack2(float lo, float hi){
  ull r; asm("mov.b64 %0, {%1,%2};" : "=l"(r) : "f"(lo), "f"(hi)); return r;
}
__device__ __forceinline__ void unpack2(ull a, float& lo, float& hi){
  asm("mov.b64 {%0,%1}, %2;" : "=f"(lo), "=f"(hi) : "l"(a));
}
__device__ __forceinline__ float sigmoidf_(float x){ return 1.0f/(1.0f+expf(-x)); }
__device__ __forceinline__ void cp16(void* sdst, const void* gsrc){
  unsigned sa;
  asm("{.reg .u64 t; cvta.to.shared.u64 t, %1; cvt.u32.u64 %0, t;}" : "=r"(sa) : "l"(sdst));
  asm volatile("cp.async.cg.shared.global [%0], [%1], 16;" :: "r"(sa), "l"(gsrc));
}

// ================= K1: bg gather + kk GEMV =================
__global__ void __launch_bounds__(256,4) k1_kernel(
  const int* __restrict__ bg_index, const int* __restrict__ mem_prob_ids,
  const int* __restrict__ mem_resp, const int* __restrict__ mem_concepts,
  const float* __restrict__ states_mem, const float* __restrict__ concept_emb,
  const float* __restrict__ prob_emb,
  const float* __restrict__ W_bg, const float* __restrict__ b_bg)
{
  __shared__ __align__(16) float hvT[2304];
  const int tb = blockIdx.x;
  const int t = tb / B_, b = tb - t*B_;
  const int tid = threadIdx.x;

  for (int i = tid; i < 192*2; i += 256) hvT[(i>>1)*12 + 10 + (i&1)] = 0.f;
  for (int i = tid; i < SEE_*3*D_; i += 256){
    int s = i / (3*D_);
    int k = i - s*3*D_;
    int idx = bg_index[(t*B_ + b)*R_ + s];
    float val;
    if (k < D_){
      val = states_mem[(size_t)idx*D_ + k];
    } else if (k < 2*D_){
      int d = k - D_;
      float ss = 0.f; int cnt = 0;
      #pragma unroll
      for (int c = 0; c < C_; ++c){
        int kc = mem_concepts[(size_t)idx*C_ + c];
        if (kc > 0){ ss += concept_emb[(size_t)(kc-1)*D_ + d]; cnt++; }
      }
      val = ss / (cnt ? (float)cnt : 1.f);
    } else {
      int d  = k - 2*D_;
      int mp = mem_prob_ids[idx];
      val = (mp > 0) ? prob_emb[(size_t)(mp-1)*D_ + d] : 0.f;
    }
    hvT[k*12 + s] = val;
  }
  if (tid < SEE_){
    int idx = bg_index[(t*B_ + b)*R_ + tid];
    g_bgr[(size_t)tb*12 + tid] = (float)mem_resp[idx];
  }
  __syncthreads();

  for (int i = tid; i < 2304; i += 256)
    g_hv[(size_t)tb*2304 + i] = hvT[i];

  {
    int hh = tid >> 6, d = tid & 63;
    const float* Wg = W_bg + (size_t)hh*(3*D_*D_) + d;
    ull a0=0,a1=0,a2=0,a3=0,a4=0;
    #pragma unroll 2
    for (int k0 = 0; k0 < 192; k0 += 8){
      float w[8];
      #pragma unroll
      for (int u = 0; u < 8; ++u) w[u] = Wg[(size_t)(k0+u)*64];
      #pragma unroll
      for (int u = 0; u < 8; ++u){
        ull ww = pack2(w[u], w[u]);
        const ull* hv = reinterpret_cast<const ull*>(hvT + (k0+u)*12);
        ffma2(a0, hv[0], ww); ffma2(a1, hv[1], ww); ffma2(a2, hv[2], ww);
        ffma2(a3, hv[3], ww); ffma2(a4, hv[4], ww);
      }
    }
    float bb = b_bg[hh*64 + d];
    float lo, hi;
    float* o = g_kk + (size_t)tb*2560 + (size_t)hh*10*64 + d;
    unpack2(a0, lo, hi); o[0*64]=bb+lo; o[1*64]=bb+hi;
    unpack2(a1, lo, hi); o[2*64]=bb+lo; o[3*64]=bb+hi;
    unpack2(a2, lo, hi); o[4*64]=bb+lo; o[5*64]=bb+hi;
    unpack2(a3, lo, hi); o[6*64]=bb+lo; o[7*64]=bb+hi;
    unpack2(a4, lo, hi); o[8*64]=bb+lo; o[9*64]=bb+hi;
  }
}

// ================= K2: v + qv + pred_v =================
__global__ void __launch_bounds__(128,8) k2_kernel(
  const int* __restrict__ prob_id, const int* __restrict__ skills,
  const float* __restrict__ concept_emb, const float* __restrict__ prob_emb,
  const float* __restrict__ W_batch, const float* __restrict__ b_batch,
  const float* __restrict__ W_pred)
{
  __shared__ __align__(16) float v[128];
  __shared__ float red[4];
  const int tb = blockIdx.x;
  const int t = tb / B_, b = tb - t*B_;
  const int tid = threadIdx.x;

  float val;
  if (tid < D_){
    float s = 0.f; int cnt = 0;
    #pragma unroll
    for (int c = 0; c < C_; ++c){
      int k = skills[(t*B_ + b)*C_ + c];
      if (k > 0){ s += concept_emb[(size_t)(k-1)*D_ + tid]; cnt++; }
    }
    val = s / (cnt ? (float)cnt : 1.f);
  } else {
    int pid = prob_id[t*B_ + b];
    val = (pid > 0) ? prob_emb[(size_t)(pid-1)*D_ + (tid - D_)] : 0.f;
  }
  v[tid] = val;
  g_v[((size_t)b*(T_+1) + t + 1)*128 + tid] = val;
  if (t == 0) g_v[((size_t)b*(T_+1))*128 + tid] = 0.f;

  // pred_v = v · W_pred[384:512]
  {
    float p = val * W_pred[384 + tid];
    #pragma unroll
    for (int o = 16; o; o >>= 1) p += __shfl_xor_sync(0xffffffffu, p, o);
    if ((tid & 31) == 0) red[tid >> 5] = p;
  }
  __syncthreads();
  if (tid == 0) g_pv[(size_t)tb*4] = red[0]+red[1]+red[2]+red[3];

  int hh = tid >> 5, dp = tid & 31;
  const ull* Wb = reinterpret_cast<const ull*>(W_batch + (size_t)hh*(3*D_*D_)) + dp;
  ull acc = 0;
  const float4* xv = reinterpret_cast<const float4*>(v);
  #pragma unroll 2
  for (int k4 = 0; k4 < 32; ++k4){
    float4 x = xv[k4]; int k = 64 + k4*4;
    ull w0 = Wb[(size_t)(k+0)*32], w1 = Wb[(size_t)(k+1)*32];
    ull w2 = Wb[(size_t)(k+2)*32], w3 = Wb[(size_t)(k+3)*32];
    ffma2(acc, pack2(x.x,x.x), w0); ffma2(acc, pack2(x.y,x.y), w1);
    ffma2(acc, pack2(x.z,x.z), w2); ffma2(acc, pack2(x.w,x.w), w3);
  }
  float lo, hi; unpack2(acc, lo, hi);
  g_qv[(size_t)tb*256 + hh*64 + 2*dp]     = b_batch[hh*64 + 2*dp]     + lo;
  g_qv[(size_t)tb*256 + hh*64 + 2*dp + 1] = b_batch[hh*64 + 2*dp + 1] + hi;
}

// ================= foldM: M_bg, M_his =================
__global__ void __launch_bounds__(256,1) foldM_kernel(
  const float* __restrict__ Wbgint, const float* __restrict__ Whisint,
  const float* __restrict__ Winmap)
{
  __shared__ float xs[16*384];
  const int r0 = blockIdx.x*16;
  const int tid = threadIdx.x;
  for (int i = tid; i < 16*384; i += 256){
    int rr = i/384, j = i - rr*384;
    int gi = r0 + rr;
    xs[i] = (gi < 384) ? Wbgint[(size_t)gi*384 + j] : Whisint[(size_t)(gi-384)*384 + j];
  }
  __syncthreads();
  const int m = tid;
  float acc[16];
  #pragma unroll
  for (int rr = 0; rr < 16; ++rr) acc[rr] = 0.f;
  for (int j = 0; j < 384; ++j){
    float w = Winmap[(size_t)j*256 + m];
    #pragma unroll
    for (int rr = 0; rr < 16; ++rr) acc[rr] += xs[rr*384 + j]*w;
  }
  #pragma unroll
  for (int rr = 0; rr < 16; ++rr){
    int gi = r0 + rr;
    if (gi < 384) g_Mbg[(size_t)gi*256 + m] = acc[rr];
    else          g_Mhis[(size_t)(gi-384)*256 + m] = acc[rr];
  }
}

// ================= foldN: N_bg = M_bg@W_ih, N_his = M_his@W_ih, N_v = W_inmap_v@W_ih =====
__global__ void __launch_bounds__(192,1) foldN_kernel(
  const float* __restrict__ W_ih, const float* __restrict__ Winmap)
{
  __shared__ float xs[16*256];
  const int r0 = blockIdx.x*16;        // 48 blocks -> rows 0..767
  const int tid = threadIdx.x;
  for (int i = tid; i < 16*256; i += 192){
    int rr = i >> 8, j = i & 255;
    int gi = r0 + rr;
    float s;
    if (gi < 384)      s = g_Mbg[(size_t)gi*256 + j];
    else if (gi < 512) s = g_Mhis[(size_t)(gi-384)*256 + j];
    else               s = Winmap[(size_t)(gi-128)*256 + j];  // rows 384..639 of W_inmap
    xs[i] = s;
  }
  __syncthreads();
  const int m = tid;
  float acc[16];
  #pragma unroll
  for (int rr = 0; rr < 16; ++rr) acc[rr] = 0.f;
  for (int j = 0; j < 256; ++j){
    float w = W_ih[(size_t)j*192 + m];
    #pragma unroll
    for (int rr = 0; rr < 16; ++rr) acc[rr] += xs[rr*256 + j]*w;
  }
  #pragma unroll
  for (int rr = 0; rr < 16; ++rr){
    int gi = r0 + rr;
    if (gi < 384)      g_Nbg[(size_t)gi*192 + m] = acc[rr];
    else if (gi < 512) g_Nhis[(size_t)(gi-384)*192 + m] = acc[rr];
    else               g_Nv[(size_t)(gi-512)*192 + m] = acc[rr];
  }
}

// ================= foldV (parallel): wbgp, whp, vb1, vb2, sb, dw =================
__global__ void __launch_bounds__(256,1) foldV_kernel(
  const float* __restrict__ Wbgint, const float* __restrict__ Whisint,
  const float* __restrict__ Winmap, const float* __restrict__ Wpred,
  const float* __restrict__ b_bgint, const float* __restrict__ b_hisint,
  const float* __restrict__ dir_w)
{
  const int blk = blockIdx.x;
  const int tid = threadIdx.x;
  const int lane = tid & 31, wid = tid >> 5;
  if (blk < 48){                      // wbgp: warp-per-row
    int i = blk*8 + wid;
    float a = 0.f;
    #pragma unroll
    for (int j4 = 0; j4 < 12; ++j4){
      int j = j4*32 + lane;
      a += Wbgint[(size_t)i*384 + j]*Wpred[j];
    }
    #pragma unroll
    for (int o = 16; o; o >>= 1) a += __shfl_xor_sync(0xffffffffu, a, o);
    if (lane == 0) g_wbgp[i] = a;
  } else if (blk < 64){               // whp
    int i = (blk-48)*8 + wid;
    float a = 0.f;
    #pragma unroll
    for (int j4 = 0; j4 < 12; ++j4){
      int j = j4*32 + lane;
      a += Whisint[(size_t)i*384 + j]*Wpred[j];
    }
    #pragma unroll
    for (int o = 16; o; o >>= 1) a += __shfl_xor_sync(0xffffffffu, a, o);
    if (lane == 0) g_whp[i] = a;
  } else if (blk == 64 || blk == 65){ // vb1 / vb2 (thread-per-col, coalesced)
    const float* bb = (blk == 64) ? b_bgint : b_hisint;
    float a0=0.f,a1=0.f,a2=0.f,a3=0.f;
    for (int j = 0; j < 384; j += 4){
      a0 += bb[j+0]*Winmap[(size_t)(j+0)*256 + tid];
      a1 += bb[j+1]*Winmap[(size_t)(j+1)*256 + tid];
      a2 += bb[j+2]*Winmap[(size_t)(j+2)*256 + tid];
      a3 += bb[j+3]*Winmap[(size_t)(j+3)*256 + tid];
    }
    float* o = (blk == 64) ? g_vb1 : g_vb2;
    o[tid] = a0+a1+a2+a3;
  } else {                            // sb0/sb1 + dw
    if (wid < 2){
      const float* bb = (wid == 0) ? b_bgint : b_hisint;
      float a = 0.f;
      #pragma unroll
      for (int j4 = 0; j4 < 12; ++j4){
        int j = j4*32 + lane;
        a += bb[j]*Wpred[j];
      }
      #pragma unroll
      for (int o = 16; o; o >>= 1) a += __shfl_xor_sync(0xffffffffu, a, o);
      if (lane == 0) g_sb[wid] = a;
    } else if (tid == 64){
      float w0 = dir_w[0], w1 = dir_w[1];
      float m  = fmaxf(w0, w1);
      float e0 = expf(w0 - m), e1 = expf(w1 - m);
      g_dw[0] = e0/(e0+e1); g_dw[1] = e1/(e0+e1);
    }
  }
}

// ================= foldGXC: gxc = (dw0*vb1+dw1*vb2+b_inmap)@W_ih + b_ih =================
__global__ void __launch_bounds__(256,1) foldGXC_kernel(
  const float* __restrict__ W_ih, const float* __restrict__ b_inmap,
  const float* __restrict__ b_ih)
{
  __shared__ float big[256];
  const int tid = threadIdx.x;
  big[tid] = g_dw[0]*g_vb1[tid] + g_dw[1]*g_vb2[tid] + b_inmap[tid];
  __syncthreads();
  if (tid < 192){
    float a0=0.f,a1=0.f,a2=0.f,a3=0.f;
    for (int j = 0; j < 256; j += 4){
      a0 += big[j+0]*W_ih[(size_t)(j+0)*192 + tid];
      a1 += big[j+1]*W_ih[(size_t)(j+1)*192 + tid];
      a2 += big[j+2]*W_ih[(size_t)(j+2)*192 + tid];
      a3 += big[j+3]*W_ih[(size_t)(j+3)*192 + tid];
    }
    g_gxc[tid] = b_ih[tid] + a0+a1+a2+a3;
  }
}

// ================= kGXV: gxv[tb] = v @ N_v[rf-half] =================
__global__ void __launch_bounds__(768,1) kGXV_kernel(const int* __restrict__ response)
{
  __shared__ __align__(16) float vs[16*128];
  __shared__ int rf[16];
  const int tb0 = blockIdx.x*16;
  const int tid = threadIdx.x;
  for (int i = tid; i < 16*128; i += 768){
    int ii = i >> 7, c = i & 127;
    int tb = tb0 + ii;
    int t = tb / B_, b = tb - t*B_;
    vs[i] = g_v[((size_t)b*(T_+1) + t + 1)*128 + c];
  }
  if (tid < 16) rf[tid] = response[tb0 + tid];
  __syncthreads();

  int tbs = tid / 48, u = tid - tbs*48;
  const float* vrow = vs + tbs*128;
  int base = rf[tbs] ? 0 : 128;
  const ulonglong2* Np = reinterpret_cast<const ulonglong2*>(g_Nv) + (size_t)base*48 + u;
  ull a0 = 0, a1 = 0;
  #pragma unroll 4
  for (int k = 0; k < 128; ++k){
    float xk = vrow[k];
    ulonglong2 w = Np[(size_t)k*48];
    ull xx = pack2(xk, xk);
    ffma2(a0, xx, w.x); ffma2(a1, xx, w.y);
  }
  float l0,h0,l1,h1; unpack2(a0,l0,h0); unpack2(a1,l1,h1);
  *reinterpret_cast<float4*>(g_gxv + (size_t)(tb0+tbs)*192 + 4*u) = make_float4(l0,h0,l1,h1);
}

// ================= kK2 =================
__global__ void __launch_bounds__(1024,1) kK2_kernel(const float* __restrict__ W_batch)
{
  extern __shared__ float sK2[];
  float* WbT = sK2;
  float* kks = sK2 + 4*4352;
  const int tid = threadIdx.x;

  for (int i = tid; i < 4*64*64; i += 1024){
    int h = i >> 12, rem = i & 4095, e = rem >> 6, d = rem & 63;
    WbT[h*4352 + d*68 + e] = W_batch[(size_t)h*12288 + e*64 + d];
  }
  for (int i = tid; i < 8*2560; i += 1024){
    int tb = i / 2560, r = i - tb*2560;
    kks[i] = g_kk[((size_t)blockIdx.x*8 + tb)*2560 + r];
  }
  __syncthreads();

  {
    int tb = tid >> 7, rem = tid & 127;
    int h = rem >> 5, rem2 = rem & 31;
    int sg = rem2 >> 4, eg = rem2 & 15;
    int p0 = h*10 + sg*5, e0 = eg*4;
    const float* wb = WbT + h*4352 + e0;
    const float* kr = kks + tb*2560 + p0*64;
    float4 acc[5];
    #pragma unroll
    for (int i = 0; i < 5; ++i) acc[i] = make_float4(0.f,0.f,0.f,0.f);
    #pragma unroll 4
    for (int d = 0; d < 64; ++d){
      float4 w = *reinterpret_cast<const float4*>(wb + d*68);
      #pragma unroll
      for (int i = 0; i < 5; ++i){
        float kv = kr[i*64 + d];
        acc[i].x += kv*w.x; acc[i].y += kv*w.y;
        acc[i].z += kv*w.z; acc[i].w += kv*w.w;
      }
    }
    size_t tbg = (size_t)blockIdx.x*8 + tb;
    #pragma unroll
    for (int i = 0; i < 5; ++i)
      *reinterpret_cast<float4*>(g_K2 + tbg*2560 + (p0+i)*64 + e0) = acc[i];
  }
  if (tid < 320){
    int tb = tid / 40, p = tid - tb*40, h = p/10;
    size_t tbg = (size_t)blockIdx.x*8 + tb;
    const float* qv = g_qv + tbg*256 + h*64;
    const float* kr = kks + tb*2560 + p*64;
    float acc = 0.f;
    #pragma unroll 4
    for (int d = 0; d < 64; ++d) acc += qv[d]*kr[d];
    g_pc[tbg*40 + p] = acc;
  }
}

// ================= K3: history softmax weights =================
__global__ void __launch_bounds__(512,1) k3_kernel(const int* __restrict__ response)
{
  extern __shared__ float k3s[];
  float* vv   = k3s;
  float* resp = k3s + (T_+1)*129;
  const int b   = blockIdx.x;
  const int tid = threadIdx.x;
  const int lane = tid & 31, wid = tid >> 5;
  const float inv_s128 = 1.0f/sqrtf(128.0f);

  for (int i = tid; i < (T_+1)*128; i += 512){
    int row = i >> 7, col = i & 127;
    vv[row*129 + col] = g_v[(size_t)b*(T_+1)*128 + i];
  }
  for (int j = tid; j <= T_; j += 512)
    resp[j] = (j == 0) ? 0.f : (float)response[(j-1)*B_ + b];
  __syncthreads();

  for (int t = wid; t < T_; t += 16){
    const float* vt = vv + (t+1)*129;
    float scv[4]; int nj = 0;
    for (int j = lane; j <= t; j += 32){
      const float* vj = vv + j*129;
      float a = 0.f;
      #pragma unroll 4
      for (int k = 0; k < 128; ++k) a += vt[k]*vj[k];
      scv[nj++] = a * inv_s128;
    }
    float mx = -1e30f;
    for (int i = 0; i < nj; ++i) mx = fmaxf(mx, scv[i]);
    #pragma unroll
    for (int o = 16; o; o >>= 1) mx = fmaxf(mx, __shfl_xor_sync(0xffffffffu, mx, o));
    float sum = 0.f;
    for (int i = 0; i < nj; ++i){ scv[i] = expf(scv[i]-mx); sum += scv[i]; }
    #pragma unroll
    for (int o = 16; o; o >>= 1) sum += __shfl_xor_sync(0xffffffffu, sum, o);
    float inv = 1.f/sum;
    int i = 0;
    for (int j = lane; j <= t; j += 32, ++i){
      float p = scv[i]*inv;
      float rb = resp[j];
      g_pr[((size_t)b*T_ + t)*132 + j] = p*rb;
      g_pn[((size_t)b*T_ + t)*132 + j] = p*(1.f-rb);
    }
    for (int j = t+1+lane; j < 132; j += 32){
      g_pr[((size_t)b*T_ + t)*132 + j] = 0.f;
      g_pn[((size_t)b*T_ + t)*132 + j] = 0.f;
    }
  }
}

// ================= K4: sequential recurrence =================
struct __align__(16) SmemSeq {
  alignas(16) float partA[16*192];
  alignas(16) float partB[4*192];
  alignas(16) float partD[2*192];
  alignas(16) float h[64];
  alignas(16) float his[128];
  alignas(16) float bg_atts[384];
  alignas(16) float gh[192];
  alignas(16) float hbufT[64*132];
  alignas(16) float K2s[2][2560];
  alignas(16) float pcs[2][40];
  alignas(16) float hvT[2][2304];
  alignas(16) float pr[2][132];
  alignas(16) float pn[2][132];
  alignas(16) float gxv[2][192];
  alignas(16) float pv[2][4];
  alignas(16) float bgr[2][12];
  alignas(16) float wbgp_s[384];
  alignas(16) float whp_s[128];
  alignas(16) float gxc_s[192];
  alignas(16) float wpredh_s[64];
  alignas(16) float bhh_s[192];
  float logit[40], att[40], ws[12];
  float pred_h, pred_his, predbg;
  float dw0, dw1, sb0, sb1, bp0;
};

__device__ __forceinline__ void do_prefetch(SmemSeq* sm, int b, int tn, int nb,
                                            int idx, int nthr)
{
  size_t tb = (size_t)tn*B_ + b;
  float* d0 = sm->K2s[nb]; const float* s0 = g_K2 + tb*2560;
  float* d1 = sm->hvT[nb]; const float* s1 = g_hv + tb*2304;
  float* d3 = sm->pcs[nb]; const float* s3 = g_pc + tb*40;
  float* d4 = sm->pr[nb];  const float* s4 = g_pr + ((size_t)b*T_ + tn)*132;
  float* d5 = sm->pn[nb];  const float* s5 = g_pn + ((size_t)b*T_ + tn)*132;
  float* d6 = sm->bgr[nb]; const float* s6 = g_bgr + tb*12;
  float* d7 = sm->gxv[nb]; const float* s7 = g_gxv + tb*192;
  float* d8 = sm->pv[nb];  const float* s8 = g_pv + tb*4;
  for (int u = idx; u < 640; u += nthr) cp16(d0+4*u, s0+4*u);
  for (int u = idx; u < 576; u += nthr) cp16(d1+4*u, s1+4*u);
  for (int u = idx; u <  10; u += nthr) cp16(d3+4*u, s3+4*u);
  for (int u = idx; u <  33; u += nthr) cp16(d4+4*u, s4+4*u);
  for (int u = idx; u <  33; u += nthr) cp16(d5+4*u, s5+4*u);
  for (int u = idx; u <   3; u += nthr) cp16(d6+4*u, s6+4*u);
  for (int u = idx; u <  48; u += nthr) cp16(d7+4*u, s7+4*u);
  for (int u = idx; u <   1; u += nthr) cp16(d8+4*u, s8+4*u);
}

__device__ __forceinline__ void gemv_seg(const float* __restrict__ W, int rowlen4,
                                         const float* __restrict__ x, int k0, int nk,
                                         int u, float* __restrict__ outp)
{
  const ulonglong2* Wp = reinterpret_cast<const ulonglong2*>(W) + (size_t)k0*rowlen4 + u;
  ull a0 = 0, a1 = 0;
  #pragma unroll 4
  for (int k = 0; k < nk; ++k){
    float xk = x[k0 + k];
    ulonglong2 w = Wp[(size_t)k*rowlen4];
    ull xx = pack2(xk, xk);
    ffma2(a0, xx, w.x);
    ffma2(a1, xx, w.y);
  }
  float l0,h0,l1,h1; unpack2(a0,l0,h0); unpack2(a1,l1,h1);
  *reinterpret_cast<float4*>(outp) = make_float4(l0,h0,l1,h1);
}

__global__ void __launch_bounds__(NT,1) k4_kernel(
  const float* __restrict__ W_pred, const float* __restrict__ b_pred,
  const float* __restrict__ W_hh, const float* __restrict__ b_hh,
  const float* __restrict__ heads_map,
  float* __restrict__ out)
{
  extern __shared__ unsigned char smraw[];
  SmemSeq* sm = reinterpret_cast<SmemSeq*>(smraw);
  const int b    = blockIdx.x;
  const int tid  = threadIdx.x;
  const int lane = tid & 31;
  const int wid  = tid >> 5;
  const float inv_s192 = 1.0f/sqrtf(192.0f);

  if (tid < 64){ sm->h[tid] = 0.f; sm->hbufT[tid*132] = 0.f; }
  if (tid < 384) sm->wbgp_s[tid] = g_wbgp[tid];
  if (tid >= 384 && tid < 512) sm->whp_s[tid-384] = g_whp[tid-384];
  if (tid >= 512 && tid < 704) sm->gxc_s[tid-512] = g_gxc[tid-512];
  if (tid >= 704 && tid < 768) sm->wpredh_s[tid-704] = W_pred[512 + (tid-704)];
  if (tid >= 768 && tid < 960) sm->bhh_s[tid-768] = b_hh[tid-768];
  if (tid == 960){
    sm->dw0 = g_dw[0]; sm->dw1 = g_dw[1];
    sm->sb0 = g_sb[0]; sm->sb1 = g_sb[1];
    sm->bp0 = b_pred[0];
  }
  do_prefetch(sm, b, 0, 0, tid, NT);
  asm volatile("cp.async.commit_group;");
  __syncthreads();

  for (int t = 0; t < T_; ++t){
    const int cur = t & 1, nxt = cur ^ 1;
    asm volatile("cp.async.wait_group 0;");
    __syncthreads();

    // ===== P0: logits (0..639) | his (640..767) | prefetch (768..1023) =====
    if (tid < 640){
      int p = tid >> 4, l = tid & 15;
      float4 kv = reinterpret_cast<const float4*>(sm->K2s[cur])[p*16 + l];
      float4 hv = reinterpret_cast<const float4*>(sm->h)[l];
      float acc = kv.x*hv.x + kv.y*hv.y + kv.z*hv.z + kv.w*hv.w;
      #pragma unroll
      for (int o = 8; o; o >>= 1) acc += __shfl_xor_sync(0xffffffffu, acc, o);
      if (l == 0) sm->logit[p] = (acc + sm->pcs[cur][p]) * inv_s192;
    } else if (tid < 768){
      int u = tid - 640, d = u & 63;
      const float4* w4 = reinterpret_cast<const float4*>((u < 64) ? sm->pr[cur] : sm->pn[cur]);
      const float4* h4 = reinterpret_cast<const float4*>(sm->hbufT) + d*33;
      float a0 = 0.f, a1 = 0.f;
      int nj4 = (t >> 2) + 1;
      for (int j4 = 0; j4 < nj4; ++j4){
        float4 ww = w4[j4], hh = h4[j4];
        a0 += ww.x*hh.x + ww.y*hh.y;
        a1 += ww.z*hh.z + ww.w*hh.w;
      }
      sm->his[u] = a0 + a1;
    } else {
      if (t + 1 < T_){
        do_prefetch(sm, b, t+1, nxt, tid-768, 256);
        asm volatile("cp.async.commit_group;");
      }
    }
    __syncthreads();

    // ===== P1: softmax+ws (w0) | pred_h (w1) | pred_his (w2) | W_hh (96..191) | N_his (192..383) =====
    if (wid == 0){
      if (lane < H_){
        float mx = -1e30f;
        #pragma unroll
        for (int s = 0; s < SEE_; ++s) mx = fmaxf(mx, sm->logit[lane*10 + s]);
        float sum = 0.f;
        #pragma unroll
        for (int s = 0; s < SEE_; ++s){
          float e = expf(sm->logit[lane*10 + s] - mx);
          sm->att[lane*10 + s] = e; sum += e;
        }
        float inv = 1.f/sum;
        #pragma unroll
        for (int s = 0; s < SEE_; ++s) sm->att[lane*10 + s] *= inv;
      }
      __syncwarp();
      if (lane < SEE_){
        float a = 0.f;
        #pragma unroll
        for (int hh = 0; hh < H_; ++hh) a += heads_map[hh]*sm->att[hh*10 + lane];
        sm->ws[lane] = a;
      }
    } else if (wid == 1){
      float part = sm->h[lane]*sm->wpredh_s[lane] + sm->h[32+lane]*sm->wpredh_s[32+lane];
      #pragma unroll
      for (int o = 16; o; o >>= 1) part += __shfl_xor_sync(0xffffffffu, part, o);
      if (lane == 0) sm->pred_h = part;
    } else if (wid == 2){
      float part = 0.f;
      #pragma unroll
      for (int j = 0; j < 4; ++j){
        int i = j*32 + lane;
        part += sm->his[i] * sm->whp_s[i];
      }
      #pragma unroll
      for (int o = 16; o; o >>= 1) part += __shfl_xor_sync(0xffffffffu, part, o);
      if (lane == 0) sm->pred_his = part;
    } else if (tid >= 96 && tid < 192){
      int i = tid - 96, seg = i / 48, u = i - seg*48;
      gemv_seg(W_hh, 48, sm->h, seg*32, 32, u, &sm->partD[seg*192 + 4*u]);
    } else if (tid >= 192 && tid < 384){
      int i = tid - 192, seg = i / 48, u = i - seg*48;
      gemv_seg(g_Nhis, 48, sm->his, seg*32, 32, u, &sm->partB[seg*192 + 4*u]);
    }
    __syncthreads();

    // ===== P2: bg_atts (0..383) | gh combine (384..575) =====
    if (tid < 384){
      bool lo_ = tid < 192;
      int kidx = lo_ ? tid : tid - 192;
      float acc = 0.f;
      #pragma unroll
      for (int s = 0; s < SEE_; ++s){
        float r = sm->bgr[cur][s];
        acc += sm->ws[s] * sm->hvT[cur][kidx*12 + s] * (lo_ ? r : (1.f - r));
      }
      sm->bg_atts[tid] = acc;
    } else if (tid < 576){
      int j = tid - 384;
      sm->gh[j] = sm->bhh_s[j] + sm->partD[j] + sm->partD[192 + j];
    }
    __syncthreads();

    // ===== P3: N_bg GEMV (0..767) | predbg (768..799) =====
    if (tid < 768){
      int seg = tid / 48, u = tid - seg*48;
      gemv_seg(g_Nbg, 48, sm->bg_atts, seg*24, 24, u, &sm->partA[seg*192 + 4*u]);
    } else if (tid < 800){
      int l = tid - 768;
      float part = 0.f;
      #pragma unroll
      for (int j = 0; j < 12; ++j){
        int i = j*32 + l;
        part += sm->bg_atts[i] * sm->wbgp_s[i];
      }
      #pragma unroll
      for (int o = 16; o; o >>= 1) part += __shfl_xor_sync(0xffffffffu, part, o);
      if (l == 0) sm->predbg = part;
    }
    __syncthreads();

    // ===== P4: gx combine + GRU (0..63) | out (64) =====
    if (tid < 64){
      int d = tid;
      float sAr=0.f,sAz=0.f,sAn=0.f;
      #pragma unroll
      for (int s = 0; s < 16; ++s){
        const float* pa = sm->partA + s*192;
        sAr += pa[d]; sAz += pa[64+d]; sAn += pa[128+d];
      }
      float sBr=0.f,sBz=0.f,sBn=0.f;
      #pragma unroll
      for (int s = 0; s < 4; ++s){
        const float* pb = sm->partB + s*192;
        sBr += pb[d]; sBz += pb[64+d]; sBn += pb[128+d];
      }
      float gr = sm->gxc_s[d]      + sm->gxv[cur][d]      + sm->dw0*sAr + sm->dw1*sBr;
      float gz = sm->gxc_s[64+d]   + sm->gxv[cur][64+d]   + sm->dw0*sAz + sm->dw1*sBz;
      float gn = sm->gxc_s[128+d]  + sm->gxv[cur][128+d]  + sm->dw0*sAn + sm->dw1*sBn;
      float r  = sigmoidf_(gr + sm->gh[d]);
      float z  = sigmoidf_(gz + sm->gh[64+d]);
      float n  = tanhf   (gn + r*sm->gh[128+d]);
      float nh = (1.f - z)*n + z*sm->h[d];
      sm->h[d] = nh;
      sm->hbufT[d*132 + (t+1)] = nh;
    } else if (tid == 64){
      out[b*T_ + t] = sm->bp0 + sm->pv[cur][0] + sm->pred_h
                    + sm->dw0*(sm->predbg + sm->sb0)
                    + sm->dw1*(sm->pred_his + sm->sb1);
    }
    __syncthreads();
  }
}

extern "C" void kernel_launch(void* const* d_in, const int* in_sizes, int n_in,
                              void* d_out, int out_size)
{
  (void)in_sizes; (void)n_in; (void)out_size;

  const int*   prob_id      = (const int*)  d_in[0];
  const int*   skills       = (const int*)  d_in[1];
  const int*   response     = (const int*)  d_in[2];
  const int*   bg_index     = (const int*)  d_in[3];
  const int*   mem_prob_ids = (const int*)  d_in[4];
  const int*   mem_resp     = (const int*)  d_in[5];
  const int*   mem_concepts = (const int*)  d_in[6];
  const float* states_mem   = (const float*)d_in[7];
  const float* concept_emb  = (const float*)d_in[8];
  const float* prob_emb     = (const float*)d_in[9];
  const float* W_pred       = (const float*)d_in[10];
  const float* b_pred       = (const float*)d_in[11];
  const float* W_ih         = (const float*)d_in[12];
  const float* W_hh         = (const float*)d_in[13];
  const float* b_ih         = (const float*)d_in[14];
  const float* b_hh         = (const float*)d_in[15];
  const float* W_batch      = (const float*)d_in[16];
  const float* b_batch      = (const float*)d_in[17];
  const float* W_bg         = (const float*)d_in[18];
  const float* b_bg         = (const float*)d_in[19];
  const float* W_bgint      = (const float*)d_in[20];
  const float* b_bgint      = (const float*)d_in[21];
  const float* W_hisint     = (const float*)d_in[22];
  const float* b_hisint     = (const float*)d_in[23];
  const float* W_inmap      = (const float*)d_in[24];
  const float* b_inmap      = (const float*)d_in[25];
  const float* dir_w        = (const float*)d_in[26];
  const float* heads_map    = (const float*)d_in[27];

  k1_kernel<<<T_*B_, 256>>>(bg_index, mem_prob_ids, mem_resp, mem_concepts,
                            states_mem, concept_emb, prob_emb, W_bg, b_bg);
  k2_kernel<<<T_*B_, 128>>>(prob_id, skills, concept_emb, prob_emb,
                            W_batch, b_batch, W_pred);
  foldM_kernel<<<32, 256>>>(W_bgint, W_hisint, W_inmap);
  foldV_kernel<<<67, 256>>>(W_bgint, W_hisint, W_inmap, W_pred,
                            b_bgint, b_hisint, dir_w);
  foldN_kernel<<<48, 192>>>(W_ih, W_inmap);
  foldGXC_kernel<<<1, 256>>>(W_ih, b_inmap, b_ih);

  int kK2smem = (4*4352 + 8*2560) * (int)sizeof(float);
  cudaFuncSetAttribute(kK2_kernel, cudaFuncAttributeMaxDynamicSharedMemorySize, kK2smem);
  kK2_kernel<<<T_*B_/8, 1024, kK2smem>>>(W_batch);

  int k3smem = ((T_+1)*129 + 132) * (int)sizeof(float);
  cudaFuncSetAttribute(k3_kernel, cudaFuncAttributeMaxDynamicSharedMemorySize, k3smem);
  k3_kernel<<<B_, 512, k3smem>>>(response);

  kGXV_kernel<<<T_*B_/16, 768>>>(response);

  cudaFuncSetAttribute(k4_kernel, cudaFuncAttributeMaxDynamicSharedMemorySize,
                       (int)sizeof(SmemSeq));
  k4_kernel<<<B_, NT, sizeof(SmemSeq)>>>(
    W_pred, b_pred, W_hh, b_hh, heads_map, (float*)d_out);
}